// round 11
// baseline (speedup 1.0000x reference)
#include <cuda_runtime.h>
#include <cstdint>

#define BATCH   16384
#define SEQ_L   64
#define T_STEPS 32
#define NH      128
#define TPC     64
#define NCTA    (BATCH / TPC)   // 256
#define THREADS 512

// ---------------- smem layout (bytes) ----------------
#define S_BW   0                 // packed B-frags [9kc][8cg][2f][32lane][4g] uint2 = 147456
#define S_A0   147456            // h tile parity 0, bf16 [64][136]                 = 17408
#define S_A1   164864            // h tile parity 1                                 = 17408
#define S_AUG  182272            // aug A [2 par][64 rows][48B]: d0,d1,1,0...       = 6144
#define S_P    188416            // uint8 patch idx [32][64]                        = 2048
#define S_PART 190464            // f32 partials [2 par][8 cg][64 row][4 o]         = 16384
#define S_W2T  206848            // float4 w2T [128 col][4 o]                       = 2048
#define SMEM_TOTAL 208896
#define A_BUFSZ 17408
#define AUG_BUFSZ 3072

// ---------------- helpers ----------------
__device__ __forceinline__ uint32_t s2u(const void* p) {
    uint32_t a;
    asm("{ .reg .u64 t; cvta.to.shared.u64 t, %1; cvt.u32.u64 %0, t; }" : "=r"(a) : "l"(p));
    return a;
}
__device__ __forceinline__ uint32_t bf2(float lo, float hi) {
    uint32_t r; asm("cvt.rn.bf16x2.f32 %0, %1, %2;" : "=r"(r) : "f"(hi), "f"(lo)); return r;
}
__device__ __forceinline__ void ldm4(uint32_t* a, uint32_t addr) {
    asm volatile("ldmatrix.sync.aligned.m8n8.x4.shared.b16 {%0,%1,%2,%3}, [%4];"
        : "=r"(a[0]), "=r"(a[1]), "=r"(a[2]), "=r"(a[3]) : "r"(addr));
}
__device__ __forceinline__ void mma16(float* d, const uint32_t* a, uint32_t b0, uint32_t b1) {
    asm volatile("mma.sync.aligned.m16n8k16.row.col.f32.bf16.bf16.f32 "
        "{%0,%1,%2,%3},{%4,%5,%6,%7},{%8,%9},{%0,%1,%2,%3};"
        : "+f"(d[0]), "+f"(d[1]), "+f"(d[2]), "+f"(d[3])
        : "r"(a[0]), "r"(a[1]), "r"(a[2]), "r"(a[3]), "r"(b0), "r"(b1));
}
__device__ __forceinline__ float tanha(float x) {
    float y; asm("tanh.approx.f32 %0,%1;" : "=f"(y) : "f"(x)); return y;
}
__device__ __forceinline__ float siga(float x) {
    return fmaf(0.5f, tanha(0.5f * x), 0.5f);
}

// ============================================================================
// Fused PRNN. 64 samples/CTA, 512 threads (16 warps).
// Warp = (cg 0..7, rh 0..1): rows [32rh,+32) x cols [16cg,+16).
// K augmented with (d0, d1, 1): xi for r/z gates and all biases are folded
// INTO the MMA via a 9th k-chunk; only xi_n stays in registers (12 regs,
// staging-order-identical adds). No xi table -> ~1/3 less smem traffic.
// ============================================================================
__global__ __launch_bounds__(THREADS, 1) void prnn_kernel(
    const float* __restrict__ x, const float* __restrict__ w_ih,
    const float* __restrict__ w_hh, const float* __restrict__ b_ih,
    const float* __restrict__ b_hh, const float* __restrict__ w1,
    const float* __restrict__ b1, const float* __restrict__ w2,
    const float* __restrict__ b2, float* __restrict__ out)
{
    extern __shared__ char sm[];
    unsigned char* sP = (unsigned char*)(sm + S_P);
    float*  sPart = (float*)(sm + S_PART);
    float4* sW2T = (float4*)(sm + S_W2T);

    const int tid = threadIdx.x;
    const int wid = tid >> 5, lane = tid & 31;
    const int rg = lane >> 2, c4 = lane & 3;
    const int cg = wid & 7, rh = wid >> 3;
    const int j0 = cg * 16;
    const int rbase = rh * 32;
    const int bBase = blockIdx.x * TPC;
    const uint32_t saB = s2u(sm + S_A0);
    const uint32_t saAug = s2u(sm + S_AUG);

    // ---- stage packed B-frags (9 k-chunks; kc=8 is the xi/bias chunk) ----
    for (int i = tid; i < 18432; i += THREADS) {
        int g = i & 3, ln = (i >> 2) & 31, f = (i >> 7) & 1;
        int cgs = (i >> 8) & 7, kc = i >> 11;
        int nrow = (cgs * 2 + f) * 8 + (ln >> 2);
        uint2 val;
        if (kc < 8) {
            const float* wr = (g < 3) ? (w_hh + (g * NH + nrow) * NH) : (w1 + nrow * NH);
            wr += kc * 16 + (ln & 3) * 2;
            val = make_uint2(bf2(wr[0], wr[1]), bf2(wr[8], wr[9]));
        } else {
            // k: 0 -> w_ih[:,0], 1 -> w_ih[:,1], 2 -> bias, else 0
            float vk0 = (g < 2) ? w_ih[(g * NH + nrow) * 2] : 0.0f;
            float vk1 = (g < 2) ? w_ih[(g * NH + nrow) * 2 + 1] : 0.0f;
            float vk2 = (g == 0) ? (b_ih[nrow] + b_hh[nrow])
                      : (g == 1) ? (b_ih[NH + nrow] + b_hh[NH + nrow])
                      : (g == 2) ? b_hh[2 * NH + nrow] : 0.0f;
            int k0 = (ln & 3) * 2;
            float v0 = (k0 == 0) ? vk0 : (k0 == 2) ? vk2 : 0.0f;
            float v1 = (k0 == 0) ? vk1 : 0.0f;
            val = make_uint2(bf2(v0, v1), 0u);
        }
        ((uint2*)(sm + S_BW))[i] = val;
    }
    // ---- w2 transposed table ----
    for (int i = tid; i < NH; i += THREADS)
        sW2T[i] = make_float4(w2[i], w2[NH + i], w2[2 * NH + i], w2[3 * NH + i]);
    // ---- patch indices ----
    for (int i = tid; i < T_STEPS * TPC; i += THREADS) {
        int t = i >> 6, s = i & 63;
        const float* xb = x + (size_t)(bBase + s) * SEQ_L + 2 * t;
        sP[i] = (unsigned char)((xb[0] != 0.0f ? 1 : 0) | (xb[1] != 0.0f ? 2 : 0));
    }
    // ---- zero A buffers + aug buffers ----
    for (int i = tid; i < 2 * A_BUFSZ / 4; i += THREADS) ((uint32_t*)(sm + S_A0))[i] = 0u;
    for (int i = tid; i < 2 * AUG_BUFSZ / 4; i += THREADS) ((uint32_t*)(sm + S_AUG))[i] = 0u;
    __syncthreads();
    // aug col2 = 1.0 (both parities, constant)
    for (int i = tid; i < 2 * 64; i += THREADS) {
        int par = i >> 6, row = i & 63;
        *(uint32_t*)(sm + S_AUG + par * AUG_BUFSZ + row * 48 + 4) = bf2(1.0f, 0.0f);
    }

    // ---- per-thread consts: xi_n pieces + b1 (4 cols each) ----
    float baseN[4], wN0[4], wN1[4], b1c[4];
    #pragma unroll
    for (int ci = 0; ci < 4; ci++) {
        int col = j0 + (ci >> 1) * 8 + 2 * c4 + (ci & 1);
        baseN[ci] = b_ih[2 * NH + col];
        wN0[ci] = w_ih[(2 * NH + col) * 2];
        wN1[ci] = w_ih[(2 * NH + col) * 2 + 1];
        b1c[ci] = b1[col];
    }
    const float b2r = b2[tid & 3];

    float hp[2][2][4];
    #pragma unroll
    for (int m = 0; m < 2; m++)
        #pragma unroll
        for (int f = 0; f < 2; f++)
            #pragma unroll
            for (int e = 0; e < 4; e++) hp[m][f][e] = 0.0f;
    float acc = 0.0f;

    const uint32_t lmBase = saB + (uint32_t)(rbase + (lane & 15)) * 272 + (uint32_t)(lane >> 4) * 16;
    const uint32_t lmAug = saAug + (uint32_t)(rbase + (lane & 15)) * 48 + (uint32_t)(lane >> 4) * 16;

    for (int t = 0; t <= T_STEPS + 1; t++) {
        __syncthreads();   // sA/aug[t&1] and sPart[(t-1)&1] complete

        const uint32_t abuf = (uint32_t)(t & 1) * A_BUFSZ;
        const uint32_t gbuf = (uint32_t)(t & 1) * AUG_BUFSZ;

        // ---------- merged MMA: gates (step t, xi folded) + hid (step t-1) ----------
        float aR[2][2][4], aZ[2][2][4], aN[2][2][4], aH[2][2][4];
        #pragma unroll
        for (int m = 0; m < 2; m++)
            #pragma unroll
            for (int f = 0; f < 2; f++)
                #pragma unroll
                for (int e = 0; e < 4; e++) {
                    aR[m][f][e] = 0.f; aZ[m][f][e] = 0.f; aN[m][f][e] = 0.f; aH[m][f][e] = 0.f;
                }
        if (t <= T_STEPS) {
            #pragma unroll
            for (int kc = 0; kc < 9; kc++) {
                uint32_t A[2][4];
                #pragma unroll
                for (int m = 0; m < 2; m++) {
                    if (kc < 8) ldm4(A[m], lmBase + abuf + m * 16 * 272 + kc * 32);
                    else        ldm4(A[m], lmAug + gbuf + m * 16 * 48);
                }
                #pragma unroll
                for (int f = 0; f < 2; f++) {
                    const uint4* bp = (const uint4*)(sm + S_BW +
                        ((size_t)(((kc * 8 + cg) * 2 + f) * 32 + lane)) * 32);
                    uint4 B01 = bp[0];          // r frag (x,y), z frag (z,w)
                    uint4 B23 = bp[1];          // n frag (x,y), hid frag (z,w)
                    if (t < T_STEPS) {
                        #pragma unroll
                        for (int m = 0; m < 2; m++) {
                            mma16(aR[m][f], A[m], B01.x, B01.y);
                            mma16(aZ[m][f], A[m], B01.z, B01.w);
                            mma16(aN[m][f], A[m], B23.x, B23.y);
                        }
                    }
                    if (t >= 1) {
                        #pragma unroll
                        for (int m = 0; m < 2; m++) mma16(aH[m][f], A[m], B23.z, B23.w);
                    }
                }
            }
        }

        // ---------- logits + logsumexp for step t-2 (under MMA shadow) ----------
        if (t >= 2 && tid < 256) {
            int row = tid >> 2;
            const float* pb = sPart + (size_t)((t - 1) & 1) * 2048 + row * 4 + (tid & 3);
            float l = b2r;
            #pragma unroll
            for (int w = 0; w < 8; w++) l += pb[w * 256];
            float m1 = fmaxf(l, __shfl_xor_sync(0xffffffffu, l, 1));
            float mx = fmaxf(m1, __shfl_xor_sync(0xffffffffu, m1, 2));
            float e = __expf(l - mx);
            float s = e + __shfl_xor_sync(0xffffffffu, e, 1);
            s += __shfl_xor_sync(0xffffffffu, s, 2);
            float lse = mx + __logf(s);
            int idx = sP[(t - 2) * TPC + row];
            float lpick = __shfl_sync(0xffffffffu, l, (lane & ~3) | idx);
            if ((tid & 3) == 0) acc += lpick - lse;
        }

        // ---------- gate epilogue: h_t -> sA[(t+1)&1]; d_{t+1} -> aug[(t+1)&1] ----------
        if (t < T_STEPS) {
            const uint32_t wbuf = (uint32_t)((t + 1) & 1) * A_BUFSZ;
            const uint32_t waug = (uint32_t)((t + 1) & 1) * AUG_BUFSZ;
            #pragma unroll
            for (int m = 0; m < 2; m++)
                #pragma unroll
                for (int rr = 0; rr < 2; rr++) {
                    int row = rbase + m * 16 + rg + rr * 8;
                    int v = (t > 0) ? sP[(t - 1) * TPC + row] : 0;
                    if (c4 == 0) {   // write next step's input bits for this row
                        int vn = sP[t * TPC + row];
                        *(uint32_t*)(sm + S_AUG + waug + row * 48) =
                            bf2((float)(vn & 1), (float)(vn >> 1));
                    }
                    #pragma unroll
                    for (int f = 0; f < 2; f++) {
                        float hh[2];
                        #pragma unroll
                        for (int lo = 0; lo < 2; lo++) {
                            int ci = f * 2 + lo, e = rr * 2 + lo;
                            float xn = baseN[ci];
                            if (v & 1) xn += wN0[ci];
                            if (v & 2) xn += wN1[ci];
                            float r = siga(aR[m][f][e]);
                            float z = siga(aZ[m][f][e]);
                            float n = tanha(xn + r * aN[m][f][e]);
                            float h = n + z * (hp[m][f][e] - n);
                            hp[m][f][e] = h;
                            hh[lo] = h;
                        }
                        int col0 = j0 + f * 8 + 2 * c4;
                        *(uint32_t*)(sm + S_A0 + wbuf + row * 272 + col0 * 2) = bf2(hh[0], hh[1]);
                    }
                }
        }

        // ---------- head partials for step t-1 -> sPart[t&1] ----------
        if (t >= 1 && t <= T_STEPS) {
            float4 wci[4];
            #pragma unroll
            for (int ci = 0; ci < 4; ci++)
                wci[ci] = sW2T[j0 + (ci >> 1) * 8 + 2 * c4 + (ci & 1)];
            float p[4][4];
            #pragma unroll
            for (int q = 0; q < 4; q++)
                #pragma unroll
                for (int o = 0; o < 4; o++) p[q][o] = 0.0f;
            #pragma unroll
            for (int m = 0; m < 2; m++)
                #pragma unroll
                for (int f = 0; f < 2; f++)
                    #pragma unroll
                    for (int e = 0; e < 4; e++) {
                        int ci = f * 2 + (e & 1);
                        int q = m * 2 + (e >> 1);
                        float hid = fmaxf(aH[m][f][e] + b1c[ci], 0.0f);
                        p[q][0] = fmaf(hid, wci[ci].x, p[q][0]);
                        p[q][1] = fmaf(hid, wci[ci].y, p[q][1]);
                        p[q][2] = fmaf(hid, wci[ci].z, p[q][2]);
                        p[q][3] = fmaf(hid, wci[ci].w, p[q][3]);
                    }
            #pragma unroll
            for (int q = 0; q < 4; q++)
                #pragma unroll
                for (int o = 0; o < 4; o++) {
                    float v = p[q][o];
                    v += __shfl_xor_sync(0xffffffffu, v, 1);
                    v += __shfl_xor_sync(0xffffffffu, v, 2);
                    p[q][o] = v;
                }
            if (c4 == 0) {
                float4* dst = (float4*)(sPart + (size_t)(t & 1) * 2048 + cg * 256);
                #pragma unroll
                for (int q = 0; q < 4; q++) {
                    int row = rbase + (q >> 1) * 16 + rg + (q & 1) * 8;
                    dst[row] = make_float4(p[q][0], p[q][1], p[q][2], p[q][3]);
                }
            }
        }
    }

    if (tid < 256 && (tid & 3) == 0) out[bBase + (tid >> 2)] = acc;
}

extern "C" void kernel_launch(void* const* d_in, const int* in_sizes, int n_in,
                              void* d_out, int out_size) {
    const float* x    = (const float*)d_in[0];
    const float* w_ih = (const float*)d_in[1];
    const float* w_hh = (const float*)d_in[2];
    const float* b_ih = (const float*)d_in[3];
    const float* b_hh = (const float*)d_in[4];
    const float* w1   = (const float*)d_in[5];
    const float* b1   = (const float*)d_in[6];
    const float* w2   = (const float*)d_in[7];
    const float* b2   = (const float*)d_in[8];
    float* out = (float*)d_out;

    cudaFuncSetAttribute(prnn_kernel, cudaFuncAttributeMaxDynamicSharedMemorySize, SMEM_TOTAL);
    prnn_kernel<<<NCTA, THREADS, SMEM_TOTAL>>>(
        x, w_ih, w_hh, b_ih, b_hh, w1, b1, w2, b2, out);
}

// round 12
// speedup vs baseline: 1.0130x; 1.0130x over previous
#include <cuda_runtime.h>
#include <cstdint>

#define BATCH   16384
#define SEQ_L   64
#define T_STEPS 32
#define NH      128
#define TPC     64
#define NCTA    (BATCH / TPC)   // 256
#define THREADS 512

// ---------------- smem layout (bytes) ----------------
#define S_BW   0                 // packed B-frags [9kc][8cg][2f][32lane][4g] uint2 = 147456
#define S_A0   147456            // h tile parity 0, bf16 [64][136]                 = 17408
#define S_A1   164864            // h tile parity 1                                 = 17408
#define S_AUG  182272            // aug A [2 par][64 rows][48B]: d0,d1,1,0...       = 6144
#define S_P    188416            // uint8 patch idx [32][64]                        = 2048
#define S_PART 190464            // f32 partials [2 par][8 cg][64 row][4 o]         = 16384
#define S_W2T  206848            // float4 w2T [128 col][4 o]                       = 2048
#define SMEM_TOTAL 208896
#define A_BUFSZ 17408
#define AUG_BUFSZ 3072

// ---------------- helpers ----------------
__device__ __forceinline__ uint32_t s2u(const void* p) {
    uint32_t a;
    asm("{ .reg .u64 t; cvta.to.shared.u64 t, %1; cvt.u32.u64 %0, t; }" : "=r"(a) : "l"(p));
    return a;
}
__device__ __forceinline__ uint32_t bf2(float lo, float hi) {
    uint32_t r; asm("cvt.rn.bf16x2.f32 %0, %1, %2;" : "=r"(r) : "f"(hi), "f"(lo)); return r;
}
__device__ __forceinline__ void ldm4(uint32_t* a, uint32_t addr) {
    asm volatile("ldmatrix.sync.aligned.m8n8.x4.shared.b16 {%0,%1,%2,%3}, [%4];"
        : "=r"(a[0]), "=r"(a[1]), "=r"(a[2]), "=r"(a[3]) : "r"(addr));
}
__device__ __forceinline__ void mma16(float* d, const uint32_t* a, uint32_t b0, uint32_t b1) {
    asm volatile("mma.sync.aligned.m16n8k16.row.col.f32.bf16.bf16.f32 "
        "{%0,%1,%2,%3},{%4,%5,%6,%7},{%8,%9},{%0,%1,%2,%3};"
        : "+f"(d[0]), "+f"(d[1]), "+f"(d[2]), "+f"(d[3])
        : "r"(a[0]), "r"(a[1]), "r"(a[2]), "r"(a[3]), "r"(b0), "r"(b1));
}
__device__ __forceinline__ float tanha(float x) {
    float y; asm("tanh.approx.f32 %0,%1;" : "=f"(y) : "f"(x)); return y;
}
__device__ __forceinline__ float siga(float x) {
    return fmaf(0.5f, tanha(0.5f * x), 0.5f);
}
// named barrier: syncs `cnt` threads arriving at barrier `id`
__device__ __forceinline__ void nbar(int id, int cnt) {
    asm volatile("bar.sync %0, %1;" :: "r"(id), "r"(cnt) : "memory");
}

// ============================================================================
// Fused PRNN. 64 samples/CTA, 512 threads (16 warps).
// TWO DECOUPLED GROUPS: group g = wid>>3 owns rows [32g,32g+32) and syncs on
// named barrier 1+g only. Groups share read-only B-frags but phase-drift
// freely -> one group's MMAs overlap the other's epilogue/barrier.
// Warp within group: cg = wid&7 owns cols [16cg,16cg+16).
// K augmented with (d0,d1,1): xi r/z + biases folded into the MMA.
// ============================================================================
__global__ __launch_bounds__(THREADS, 1) void prnn_kernel(
    const float* __restrict__ x, const float* __restrict__ w_ih,
    const float* __restrict__ w_hh, const float* __restrict__ b_ih,
    const float* __restrict__ b_hh, const float* __restrict__ w1,
    const float* __restrict__ b1, const float* __restrict__ w2,
    const float* __restrict__ b2, float* __restrict__ out)
{
    extern __shared__ char sm[];
    unsigned char* sP = (unsigned char*)(sm + S_P);
    float*  sPart = (float*)(sm + S_PART);
    float4* sW2T = (float4*)(sm + S_W2T);

    const int tid = threadIdx.x;
    const int wid = tid >> 5, lane = tid & 31;
    const int rg = lane >> 2, c4 = lane & 3;
    const int cg = wid & 7, grp = wid >> 3;
    const int j0 = cg * 16;
    const int rbase = grp * 32;
    const int bBase = blockIdx.x * TPC;
    const uint32_t saB = s2u(sm + S_A0);
    const uint32_t saAug = s2u(sm + S_AUG);

    // ---- stage packed B-frags (9 k-chunks; kc=8 is the xi/bias chunk) ----
    for (int i = tid; i < 18432; i += THREADS) {
        int g = i & 3, ln = (i >> 2) & 31, f = (i >> 7) & 1;
        int cgs = (i >> 8) & 7, kc = i >> 11;
        int nrow = (cgs * 2 + f) * 8 + (ln >> 2);
        uint2 val;
        if (kc < 8) {
            const float* wr = (g < 3) ? (w_hh + (g * NH + nrow) * NH) : (w1 + nrow * NH);
            wr += kc * 16 + (ln & 3) * 2;
            val = make_uint2(bf2(wr[0], wr[1]), bf2(wr[8], wr[9]));
        } else {
            float vk0 = (g < 2) ? w_ih[(g * NH + nrow) * 2] : 0.0f;
            float vk1 = (g < 2) ? w_ih[(g * NH + nrow) * 2 + 1] : 0.0f;
            float vk2 = (g == 0) ? (b_ih[nrow] + b_hh[nrow])
                      : (g == 1) ? (b_ih[NH + nrow] + b_hh[NH + nrow])
                      : (g == 2) ? b_hh[2 * NH + nrow] : 0.0f;
            int k0 = (ln & 3) * 2;
            float v0 = (k0 == 0) ? vk0 : (k0 == 2) ? vk2 : 0.0f;
            float v1 = (k0 == 0) ? vk1 : 0.0f;
            val = make_uint2(bf2(v0, v1), 0u);
        }
        ((uint2*)(sm + S_BW))[i] = val;
    }
    for (int i = tid; i < NH; i += THREADS)
        sW2T[i] = make_float4(w2[i], w2[NH + i], w2[2 * NH + i], w2[3 * NH + i]);
    for (int i = tid; i < T_STEPS * TPC; i += THREADS) {
        int t = i >> 6, s = i & 63;
        const float* xb = x + (size_t)(bBase + s) * SEQ_L + 2 * t;
        sP[i] = (unsigned char)((xb[0] != 0.0f ? 1 : 0) | (xb[1] != 0.0f ? 2 : 0));
    }
    for (int i = tid; i < 2 * A_BUFSZ / 4; i += THREADS) ((uint32_t*)(sm + S_A0))[i] = 0u;
    for (int i = tid; i < 2 * AUG_BUFSZ / 4; i += THREADS) ((uint32_t*)(sm + S_AUG))[i] = 0u;
    __syncthreads();
    for (int i = tid; i < 2 * 64; i += THREADS) {
        int par = i >> 6, row = i & 63;
        *(uint32_t*)(sm + S_AUG + par * AUG_BUFSZ + row * 48 + 4) = bf2(1.0f, 0.0f);
    }

    // ---- per-thread consts: xi_n pieces + b1 ----
    float baseN[4], wN0[4], wN1[4], b1c[4];
    #pragma unroll
    for (int ci = 0; ci < 4; ci++) {
        int col = j0 + (ci >> 1) * 8 + 2 * c4 + (ci & 1);
        baseN[ci] = b_ih[2 * NH + col];
        wN0[ci] = w_ih[(2 * NH + col) * 2];
        wN1[ci] = w_ih[(2 * NH + col) * 2 + 1];
        b1c[ci] = b1[col];
    }
    const float b2r = b2[lane & 3];

    float hp[2][2][4];
    #pragma unroll
    for (int m = 0; m < 2; m++)
        #pragma unroll
        for (int f = 0; f < 2; f++)
            #pragma unroll
            for (int e = 0; e < 4; e++) hp[m][f][e] = 0.0f;
    float acc = 0.0f;

    const uint32_t lmBase = saB + (uint32_t)(rbase + (lane & 15)) * 272 + (uint32_t)(lane >> 4) * 16;
    const uint32_t lmAug = saAug + (uint32_t)(rbase + (lane & 15)) * 48 + (uint32_t)(lane >> 4) * 16;
    const int mybar = 1 + grp;

    __syncthreads();   // all shared init visible to both groups

    for (int t = 0; t <= T_STEPS + 1; t++) {
        nbar(mybar, 256);   // group-local: sA/aug[t&1] rows + sPart[(t-1)&1] rows done

        const uint32_t abuf = (uint32_t)(t & 1) * A_BUFSZ;
        const uint32_t gbuf = (uint32_t)(t & 1) * AUG_BUFSZ;

        // ---------- merged MMA: gates (step t, xi folded) + hid (step t-1) ----------
        float aR[2][2][4], aZ[2][2][4], aN[2][2][4], aH[2][2][4];
        #pragma unroll
        for (int m = 0; m < 2; m++)
            #pragma unroll
            for (int f = 0; f < 2; f++)
                #pragma unroll
                for (int e = 0; e < 4; e++) {
                    aR[m][f][e] = 0.f; aZ[m][f][e] = 0.f; aN[m][f][e] = 0.f; aH[m][f][e] = 0.f;
                }
        if (t <= T_STEPS) {
            #pragma unroll
            for (int kc = 0; kc < 9; kc++) {
                uint32_t A[2][4];
                #pragma unroll
                for (int m = 0; m < 2; m++) {
                    if (kc < 8) ldm4(A[m], lmBase + abuf + m * 16 * 272 + kc * 32);
                    else        ldm4(A[m], lmAug + gbuf + m * 16 * 48);
                }
                #pragma unroll
                for (int f = 0; f < 2; f++) {
                    const uint4* bp = (const uint4*)(sm + S_BW +
                        ((size_t)(((kc * 8 + cg) * 2 + f) * 32 + lane)) * 32);
                    uint4 B01 = bp[0];
                    uint4 B23 = bp[1];
                    if (t < T_STEPS) {
                        #pragma unroll
                        for (int m = 0; m < 2; m++) {
                            mma16(aR[m][f], A[m], B01.x, B01.y);
                            mma16(aZ[m][f], A[m], B01.z, B01.w);
                            mma16(aN[m][f], A[m], B23.x, B23.y);
                        }
                    }
                    if (t >= 1) {
                        #pragma unroll
                        for (int m = 0; m < 2; m++) mma16(aH[m][f], A[m], B23.z, B23.w);
                    }
                }
            }
        }

        // ---------- logits + logsumexp for step t-2 (this group's 32 rows) ----------
        if (t >= 2 && cg < 4) {
            int row = rbase + cg * 8 + (lane >> 2);
            const float* pb = sPart + (size_t)((t - 1) & 1) * 2048 + row * 4 + (lane & 3);
            float l = b2r;
            #pragma unroll
            for (int w = 0; w < 8; w++) l += pb[w * 256];
            float m1 = fmaxf(l, __shfl_xor_sync(0xffffffffu, l, 1));
            float mx = fmaxf(m1, __shfl_xor_sync(0xffffffffu, m1, 2));
            float e = __expf(l - mx);
            float s = e + __shfl_xor_sync(0xffffffffu, e, 1);
            s += __shfl_xor_sync(0xffffffffu, s, 2);
            float lse = mx + __logf(s);
            int idx = sP[(t - 2) * TPC + row];
            float lpick = __shfl_sync(0xffffffffu, l, (lane & ~3) | idx);
            if ((lane & 3) == 0) acc += lpick - lse;
        }

        // ---------- gate epilogue: h_t -> sA[(t+1)&1]; d_{t+1} -> aug ----------
        if (t < T_STEPS) {
            const uint32_t wbuf = (uint32_t)((t + 1) & 1) * A_BUFSZ;
            const uint32_t waug = (uint32_t)((t + 1) & 1) * AUG_BUFSZ;
            #pragma unroll
            for (int m = 0; m < 2; m++)
                #pragma unroll
                for (int rr = 0; rr < 2; rr++) {
                    int row = rbase + m * 16 + rg + rr * 8;
                    int v = (t > 0) ? sP[(t - 1) * TPC + row] : 0;
                    if (c4 == 0) {
                        int vn = sP[t * TPC + row];
                        *(uint32_t*)(sm + S_AUG + waug + row * 48) =
                            bf2((float)(vn & 1), (float)(vn >> 1));
                    }
                    #pragma unroll
                    for (int f = 0; f < 2; f++) {
                        float hh[2];
                        #pragma unroll
                        for (int lo = 0; lo < 2; lo++) {
                            int ci = f * 2 + lo, e = rr * 2 + lo;
                            float xn = baseN[ci];
                            if (v & 1) xn += wN0[ci];
                            if (v & 2) xn += wN1[ci];
                            float r = siga(aR[m][f][e]);
                            float z = siga(aZ[m][f][e]);
                            float n = tanha(xn + r * aN[m][f][e]);
                            float h = n + z * (hp[m][f][e] - n);
                            hp[m][f][e] = h;
                            hh[lo] = h;
                        }
                        int col0 = j0 + f * 8 + 2 * c4;
                        *(uint32_t*)(sm + S_A0 + wbuf + row * 272 + col0 * 2) = bf2(hh[0], hh[1]);
                    }
                }
        }

        // ---------- head partials for step t-1 -> sPart[t&1] ----------
        if (t >= 1 && t <= T_STEPS) {
            float4 wci[4];
            #pragma unroll
            for (int ci = 0; ci < 4; ci++)
                wci[ci] = sW2T[j0 + (ci >> 1) * 8 + 2 * c4 + (ci & 1)];
            float p[4][4];
            #pragma unroll
            for (int q = 0; q < 4; q++)
                #pragma unroll
                for (int o = 0; o < 4; o++) p[q][o] = 0.0f;
            #pragma unroll
            for (int m = 0; m < 2; m++)
                #pragma unroll
                for (int f = 0; f < 2; f++)
                    #pragma unroll
                    for (int e = 0; e < 4; e++) {
                        int ci = f * 2 + (e & 1);
                        int q = m * 2 + (e >> 1);
                        float hid = fmaxf(aH[m][f][e] + b1c[ci], 0.0f);
                        p[q][0] = fmaf(hid, wci[ci].x, p[q][0]);
                        p[q][1] = fmaf(hid, wci[ci].y, p[q][1]);
                        p[q][2] = fmaf(hid, wci[ci].z, p[q][2]);
                        p[q][3] = fmaf(hid, wci[ci].w, p[q][3]);
                    }
            #pragma unroll
            for (int q = 0; q < 4; q++)
                #pragma unroll
                for (int o = 0; o < 4; o++) {
                    float v = p[q][o];
                    v += __shfl_xor_sync(0xffffffffu, v, 1);
                    v += __shfl_xor_sync(0xffffffffu, v, 2);
                    p[q][o] = v;
                }
            if (c4 == 0) {
                float4* dst = (float4*)(sPart + (size_t)(t & 1) * 2048 + cg * 256);
                #pragma unroll
                for (int q = 0; q < 4; q++) {
                    int row = rbase + (q >> 1) * 16 + rg + (q & 1) * 8;
                    dst[row] = make_float4(p[q][0], p[q][1], p[q][2], p[q][3]);
                }
            }
        }
    }

    if (cg < 4 && (lane & 3) == 0)
        out[bBase + rbase + cg * 8 + (lane >> 2)] = acc;
}

extern "C" void kernel_launch(void* const* d_in, const int* in_sizes, int n_in,
                              void* d_out, int out_size) {
    const float* x    = (const float*)d_in[0];
    const float* w_ih = (const float*)d_in[1];
    const float* w_hh = (const float*)d_in[2];
    const float* b_ih = (const float*)d_in[3];
    const float* b_hh = (const float*)d_in[4];
    const float* w1   = (const float*)d_in[5];
    const float* b1   = (const float*)d_in[6];
    const float* w2   = (const float*)d_in[7];
    const float* b2   = (const float*)d_in[8];
    float* out = (float*)d_out;

    cudaFuncSetAttribute(prnn_kernel, cudaFuncAttributeMaxDynamicSharedMemorySize, SMEM_TOTAL);
    prnn_kernel<<<NCTA, THREADS, SMEM_TOTAL>>>(
        x, w_ih, w_hh, b_ih, b_hh, w1, b1, w2, b2, out);
}

// round 14
// speedup vs baseline: 1.0886x; 1.0746x over previous
#include <cuda_runtime.h>
#include <cuda_fp16.h>
#include <cstdint>

#define BATCH   16384
#define SEQ_L   64
#define T_STEPS 32
#define NH      128
#define TPC     64
#define NCTA    (BATCH / TPC)   // 256
#define THREADS 512

// ---------------- smem layout (bytes) ----------------
#define S_BW   0                 // packed B-frags [9kc][8cg][2f][32lane][4g] uint2 = 147456
#define S_A0   147456            // h tile parity 0, f16 [64][136]                  = 17408
#define S_A1   164864            // h tile parity 1                                 = 17408
#define S_AUG  182272            // aug A [2 par][64 rows][48B]: d0,d1,1,0...       = 6144
#define S_P    188416            // uint8 patch idx [32][64]                        = 2048
#define S_PART 190464            // f32 partials [2 par][8 cg][64 row][4 o]         = 16384
#define S_W2T  206848            // float4 w2T [128 col][4 o]                       = 2048
#define SMEM_TOTAL 208896
#define A_BUFSZ 17408
#define AUG_BUFSZ 3072

// ---------------- helpers ----------------
__device__ __forceinline__ uint32_t s2u(const void* p) {
    uint32_t a;
    asm("{ .reg .u64 t; cvta.to.shared.u64 t, %1; cvt.u32.u64 %0, t; }" : "=r"(a) : "l"(p));
    return a;
}
__device__ __forceinline__ uint32_t f2h2(float lo, float hi) {
    __half2 h = __floats2half2_rn(lo, hi);   // lo -> low half
    return *(uint32_t*)&h;
}
__device__ __forceinline__ float2 h22f2(uint32_t u) {
    return __half22float2(*(__half2*)&u);
}
__device__ __forceinline__ void ldm4(uint32_t* a, uint32_t addr) {
    asm volatile("ldmatrix.sync.aligned.m8n8.x4.shared.b16 {%0,%1,%2,%3}, [%4];"
        : "=r"(a[0]), "=r"(a[1]), "=r"(a[2]), "=r"(a[3]) : "r"(addr));
}
// f16 inputs, f32 accum (hid GEMM)
__device__ __forceinline__ void mma16f(float* d, const uint32_t* a, uint32_t b0, uint32_t b1) {
    asm volatile("mma.sync.aligned.m16n8k16.row.col.f32.f16.f16.f32 "
        "{%0,%1,%2,%3},{%4,%5,%6,%7},{%8,%9},{%0,%1,%2,%3};"
        : "+f"(d[0]), "+f"(d[1]), "+f"(d[2]), "+f"(d[3])
        : "r"(a[0]), "r"(a[1]), "r"(a[2]), "r"(a[3]), "r"(b0), "r"(b1));
}
// f16 inputs, f16 accum (gates; 2x rate, half regs)
__device__ __forceinline__ void mma16h(uint32_t* d, const uint32_t* a, uint32_t b0, uint32_t b1) {
    asm volatile("mma.sync.aligned.m16n8k16.row.col.f16.f16.f16.f16 "
        "{%0,%1},{%2,%3,%4,%5},{%6,%7},{%0,%1};"
        : "+r"(d[0]), "+r"(d[1])
        : "r"(a[0]), "r"(a[1]), "r"(a[2]), "r"(a[3]), "r"(b0), "r"(b1));
}
__device__ __forceinline__ float tanha(float x) {
    float y; asm("tanh.approx.f32 %0,%1;" : "=f"(y) : "f"(x)); return y;
}
__device__ __forceinline__ float siga(float x) {
    return fmaf(0.5f, tanha(0.5f * x), 0.5f);
}
__device__ __forceinline__ void nbar(int id, int cnt) {
    asm volatile("bar.sync %0, %1;" :: "r"(id), "r"(cnt) : "memory");
}

// ============================================================================
// Fused PRNN. 64 samples/CTA, 512 threads (16 warps), two decoupled groups.
// ALL f16 operands; gate MMAs use f16 accumulation (2x tensor rate, 24 fewer
// regs); hid MMA keeps f32 accum. Aug k-chunk folds xi r/z + biases into MMA.
// ============================================================================
__global__ __launch_bounds__(THREADS, 1) void prnn_kernel(
    const float* __restrict__ x, const float* __restrict__ w_ih,
    const float* __restrict__ w_hh, const float* __restrict__ b_ih,
    const float* __restrict__ b_hh, const float* __restrict__ w1,
    const float* __restrict__ b1, const float* __restrict__ w2,
    const float* __restrict__ b2, float* __restrict__ out)
{
    extern __shared__ char sm[];
    unsigned char* sP = (unsigned char*)(sm + S_P);
    float*  sPart = (float*)(sm + S_PART);
    float4* sW2T = (float4*)(sm + S_W2T);

    const int tid = threadIdx.x;
    const int wid = tid >> 5, lane = tid & 31;
    const int rg = lane >> 2, c4 = lane & 3;
    const int cg = wid & 7, grp = wid >> 3;
    const int j0 = cg * 16;
    const int rbase = grp * 32;
    const int bBase = blockIdx.x * TPC;
    const uint32_t saB = s2u(sm + S_A0);
    const uint32_t saAug = s2u(sm + S_AUG);

    // ---- stage packed B-frags (9 k-chunks; kc=8 is the xi/bias chunk), f16 ----
    for (int i = tid; i < 18432; i += THREADS) {
        int g = i & 3, ln = (i >> 2) & 31, f = (i >> 7) & 1;
        int cgs = (i >> 8) & 7, kc = i >> 11;
        int nrow = (cgs * 2 + f) * 8 + (ln >> 2);
        uint2 val;
        if (kc < 8) {
            const float* wr = (g < 3) ? (w_hh + (g * NH + nrow) * NH) : (w1 + nrow * NH);
            wr += kc * 16 + (ln & 3) * 2;
            val = make_uint2(f2h2(wr[0], wr[1]), f2h2(wr[8], wr[9]));
        } else {
            float vk0 = (g < 2) ? w_ih[(g * NH + nrow) * 2] : 0.0f;
            float vk1 = (g < 2) ? w_ih[(g * NH + nrow) * 2 + 1] : 0.0f;
            float vk2 = (g == 0) ? (b_ih[nrow] + b_hh[nrow])
                      : (g == 1) ? (b_ih[NH + nrow] + b_hh[NH + nrow])
                      : (g == 2) ? b_hh[2 * NH + nrow] : 0.0f;
            int k0 = (ln & 3) * 2;
            float v0 = (k0 == 0) ? vk0 : (k0 == 2) ? vk2 : 0.0f;
            float v1 = (k0 == 0) ? vk1 : 0.0f;
            val = make_uint2(f2h2(v0, v1), 0u);
        }
        ((uint2*)(sm + S_BW))[i] = val;
    }
    for (int i = tid; i < NH; i += THREADS)
        sW2T[i] = make_float4(w2[i], w2[NH + i], w2[2 * NH + i], w2[3 * NH + i]);
    for (int i = tid; i < T_STEPS * TPC; i += THREADS) {
        int t = i >> 6, s = i & 63;
        const float* xb = x + (size_t)(bBase + s) * SEQ_L + 2 * t;
        sP[i] = (unsigned char)((xb[0] != 0.0f ? 1 : 0) | (xb[1] != 0.0f ? 2 : 0));
    }
    for (int i = tid; i < 2 * A_BUFSZ / 4; i += THREADS) ((uint32_t*)(sm + S_A0))[i] = 0u;
    for (int i = tid; i < 2 * AUG_BUFSZ / 4; i += THREADS) ((uint32_t*)(sm + S_AUG))[i] = 0u;
    __syncthreads();
    for (int i = tid; i < 2 * 64; i += THREADS) {
        int par = i >> 6, row = i & 63;
        *(uint32_t*)(sm + S_AUG + par * AUG_BUFSZ + row * 48 + 4) = f2h2(1.0f, 0.0f);
    }

    // ---- per-thread consts: xi_n pieces + b1 ----
    float baseN[4], wN0[4], wN1[4], b1c[4];
    #pragma unroll
    for (int ci = 0; ci < 4; ci++) {
        int col = j0 + (ci >> 1) * 8 + 2 * c4 + (ci & 1);
        baseN[ci] = b_ih[2 * NH + col];
        wN0[ci] = w_ih[(2 * NH + col) * 2];
        wN1[ci] = w_ih[(2 * NH + col) * 2 + 1];
        b1c[ci] = b1[col];
    }
    const float b2r = b2[lane & 3];

    float hp[2][2][4];
    #pragma unroll
    for (int m = 0; m < 2; m++)
        #pragma unroll
        for (int f = 0; f < 2; f++)
            #pragma unroll
            for (int e = 0; e < 4; e++) hp[m][f][e] = 0.0f;
    float acc = 0.0f;

    const uint32_t lmBase = saB + (uint32_t)(rbase + (lane & 15)) * 272 + (uint32_t)(lane >> 4) * 16;
    const uint32_t lmAug = saAug + (uint32_t)(rbase + (lane & 15)) * 48 + (uint32_t)(lane >> 4) * 16;
    const int mybar = 1 + grp;

    __syncthreads();

    for (int t = 0; t <= T_STEPS + 1; t++) {
        nbar(mybar, 256);

        const uint32_t abuf = (uint32_t)(t & 1) * A_BUFSZ;
        const uint32_t gbuf = (uint32_t)(t & 1) * AUG_BUFSZ;

        // ---------- merged MMA: gates (f16 accum) + hid (f32 accum) ----------
        uint32_t aR[2][2][2], aZ[2][2][2], aN[2][2][2];
        float aH[2][2][4];
        #pragma unroll
        for (int m = 0; m < 2; m++)
            #pragma unroll
            for (int f = 0; f < 2; f++) {
                aR[m][f][0] = aR[m][f][1] = 0u;
                aZ[m][f][0] = aZ[m][f][1] = 0u;
                aN[m][f][0] = aN[m][f][1] = 0u;
                #pragma unroll
                for (int e = 0; e < 4; e++) aH[m][f][e] = 0.f;
            }
        if (t <= T_STEPS) {
            #pragma unroll
            for (int kc = 0; kc < 9; kc++) {
                uint32_t A[2][4];
                #pragma unroll
                for (int m = 0; m < 2; m++) {
                    if (kc < 8) ldm4(A[m], lmBase + abuf + m * 16 * 272 + kc * 32);
                    else        ldm4(A[m], lmAug + gbuf + m * 16 * 48);
                }
                #pragma unroll
                for (int f = 0; f < 2; f++) {
                    const uint4* bp = (const uint4*)(sm + S_BW +
                        ((size_t)(((kc * 8 + cg) * 2 + f) * 32 + lane)) * 32);
                    uint4 B01 = bp[0];
                    uint4 B23 = bp[1];
                    if (t < T_STEPS) {
                        #pragma unroll
                        for (int m = 0; m < 2; m++) {
                            mma16h(aR[m][f], A[m], B01.x, B01.y);
                            mma16h(aZ[m][f], A[m], B01.z, B01.w);
                            mma16h(aN[m][f], A[m], B23.x, B23.y);
                        }
                    }
                    if (t >= 1) {
                        #pragma unroll
                        for (int m = 0; m < 2; m++) mma16f(aH[m][f], A[m], B23.z, B23.w);
                    }
                }
            }
        }

        // ---------- logits + logsumexp for step t-2 (this group's rows) ----------
        if (t >= 2 && cg < 4) {
            int row = rbase + cg * 8 + (lane >> 2);
            const float* pb = sPart + (size_t)((t - 1) & 1) * 2048 + row * 4 + (lane & 3);
            float l = b2r;
            #pragma unroll
            for (int w = 0; w < 8; w++) l += pb[w * 256];
            float m1 = fmaxf(l, __shfl_xor_sync(0xffffffffu, l, 1));
            float mx = fmaxf(m1, __shfl_xor_sync(0xffffffffu, m1, 2));
            float e = __expf(l - mx);
            float s = e + __shfl_xor_sync(0xffffffffu, e, 1);
            s += __shfl_xor_sync(0xffffffffu, s, 2);
            float lse = mx + __logf(s);
            int idx = sP[(t - 2) * TPC + row];
            float lpick = __shfl_sync(0xffffffffu, l, (lane & ~3) | idx);
            if ((lane & 3) == 0) acc += lpick - lse;
        }

        // ---------- gate epilogue: h_t -> sA[(t+1)&1]; d_{t+1} -> aug ----------
        if (t < T_STEPS) {
            const uint32_t wbuf = (uint32_t)((t + 1) & 1) * A_BUFSZ;
            const uint32_t waug = (uint32_t)((t + 1) & 1) * AUG_BUFSZ;
            #pragma unroll
            for (int m = 0; m < 2; m++)
                #pragma unroll
                for (int rr = 0; rr < 2; rr++) {
                    int row = rbase + m * 16 + rg + rr * 8;
                    int v = (t > 0) ? sP[(t - 1) * TPC + row] : 0;
                    if (c4 == 0) {
                        int vn = sP[t * TPC + row];
                        *(uint32_t*)(sm + S_AUG + waug + row * 48) =
                            f2h2((float)(vn & 1), (float)(vn >> 1));
                    }
                    #pragma unroll
                    for (int f = 0; f < 2; f++) {
                        float2 vR = h22f2(aR[m][f][rr]);
                        float2 vZ = h22f2(aZ[m][f][rr]);
                        float2 vN = h22f2(aN[m][f][rr]);
                        float hh[2];
                        #pragma unroll
                        for (int lo = 0; lo < 2; lo++) {
                            int ci = f * 2 + lo, e = rr * 2 + lo;
                            float gr = lo ? vR.y : vR.x;
                            float gz = lo ? vZ.y : vZ.x;
                            float gn = lo ? vN.y : vN.x;
                            float xn = baseN[ci];
                            if (v & 1) xn += wN0[ci];
                            if (v & 2) xn += wN1[ci];
                            float r = siga(gr);
                            float z = siga(gz);
                            float n = tanha(xn + r * gn);
                            float h = n + z * (hp[m][f][e] - n);
                            hp[m][f][e] = h;
                            hh[lo] = h;
                        }
                        int col0 = j0 + f * 8 + 2 * c4;
                        *(uint32_t*)(sm + S_A0 + wbuf + row * 272 + col0 * 2) = f2h2(hh[0], hh[1]);
                    }
                }
        }

        // ---------- head partials for step t-1 -> sPart[t&1] ----------
        if (t >= 1 && t <= T_STEPS) {
            float4 wci[4];
            #pragma unroll
            for (int ci = 0; ci < 4; ci++)
                wci[ci] = sW2T[j0 + (ci >> 1) * 8 + 2 * c4 + (ci & 1)];
            float p[4][4];
            #pragma unroll
            for (int q = 0; q < 4; q++)
                #pragma unroll
                for (int o = 0; o < 4; o++) p[q][o] = 0.0f;
            #pragma unroll
            for (int m = 0; m < 2; m++)
                #pragma unroll
                for (int f = 0; f < 2; f++)
                    #pragma unroll
                    for (int e = 0; e < 4; e++) {
                        int ci = f * 2 + (e & 1);
                        int q = m * 2 + (e >> 1);
                        float hid = fmaxf(aH[m][f][e] + b1c[ci], 0.0f);
                        p[q][0] = fmaf(hid, wci[ci].x, p[q][0]);
                        p[q][1] = fmaf(hid, wci[ci].y, p[q][1]);
                        p[q][2] = fmaf(hid, wci[ci].z, p[q][2]);
                        p[q][3] = fmaf(hid, wci[ci].w, p[q][3]);
                    }
            #pragma unroll
            for (int q = 0; q < 4; q++)
                #pragma unroll
                for (int o = 0; o < 4; o++) {
                    float v = p[q][o];
                    v += __shfl_xor_sync(0xffffffffu, v, 1);
                    v += __shfl_xor_sync(0xffffffffu, v, 2);
                    p[q][o] = v;
                }
            if (c4 == 0) {
                float4* dst = (float4*)(sPart + (size_t)(t & 1) * 2048 + cg * 256);
                #pragma unroll
                for (int q = 0; q < 4; q++) {
                    int row = rbase + (q >> 1) * 16 + rg + (q & 1) * 8;
                    dst[row] = make_float4(p[q][0], p[q][1], p[q][2], p[q][3]);
                }
            }
        }
    }

    if (cg < 4 && (lane & 3) == 0)
        out[bBase + rbase + cg * 8 + (lane >> 2)] = acc;
}

extern "C" void kernel_launch(void* const* d_in, const int* in_sizes, int n_in,
                              void* d_out, int out_size) {
    const float* x    = (const float*)d_in[0];
    const float* w_ih = (const float*)d_in[1];
    const float* w_hh = (const float*)d_in[2];
    const float* b_ih = (const float*)d_in[3];
    const float* b_hh = (const float*)d_in[4];
    const float* w1   = (const float*)d_in[5];
    const float* b1   = (const float*)d_in[6];
    const float* w2   = (const float*)d_in[7];
    const float* b2   = (const float*)d_in[8];
    float* out = (float*)d_out;

    cudaFuncSetAttribute(prnn_kernel, cudaFuncAttributeMaxDynamicSharedMemorySize, SMEM_TOTAL);
    prnn_kernel<<<NCTA, THREADS, SMEM_TOTAL>>>(
        x, w_ih, w_hh, b_ih, b_hh, w1, b1, w2, b2, out);
}

// round 15
// speedup vs baseline: 1.3284x; 1.2203x over previous
#include <cuda_runtime.h>
#include <cuda_fp16.h>
#include <cstdint>

#define BATCH   16384
#define SEQ_L   64
#define T_STEPS 32
#define NH      128
#define TPC     128
#define NCTA    (BATCH / TPC)   // 128 -> exactly one wave on 148 SMs
#define THREADS 512

// ---------------- smem layout (bytes) ----------------
#define S_BW    0                // main B-frags [8kc][8cg][2f][32lane][4g] uint2 = 131072
#define S_BAUG  131072           // aug  B-frags [8cg][2f][32lane][4g] uint32     = 8192
#define S_A0    139264           // A tile parity 0: [128 rows][272B] f16
                                 //   cols 0-127 = h, col 128/129 = d0/d1, col 130 = 1
#define S_A1    174080           // A tile parity 1                               = 34816
#define S_P     208896           // uint8 patch idx [32][128]                     = 4096
#define S_PART  212992           // f32 partials [8 cg][128 row][4 o]             = 16384
#define S_W2T   229376           // float4 w2T [128 col][4 o]                     = 2048
#define SMEM_TOTAL 231424
#define A_BUFSZ 34816

// ---------------- helpers ----------------
__device__ __forceinline__ uint32_t s2u(const void* p) {
    uint32_t a;
    asm("{ .reg .u64 t; cvta.to.shared.u64 t, %1; cvt.u32.u64 %0, t; }" : "=r"(a) : "l"(p));
    return a;
}
__device__ __forceinline__ uint32_t f2h2(float lo, float hi) {
    __half2 h = __floats2half2_rn(lo, hi);
    return *(uint32_t*)&h;
}
__device__ __forceinline__ float2 h22f2(uint32_t u) {
    return __half22float2(*(__half2*)&u);
}
__device__ __forceinline__ void ldm4(uint32_t* a, uint32_t addr) {
    asm volatile("ldmatrix.sync.aligned.m8n8.x4.shared.b16 {%0,%1,%2,%3}, [%4];"
        : "=r"(a[0]), "=r"(a[1]), "=r"(a[2]), "=r"(a[3]) : "r"(addr));
}
__device__ __forceinline__ void ldm2(uint32_t* a, uint32_t addr) {
    asm volatile("ldmatrix.sync.aligned.m8n8.x2.shared.b16 {%0,%1}, [%2];"
        : "=r"(a[0]), "=r"(a[1]) : "r"(addr));
}
// f16 accum, k16
__device__ __forceinline__ void mma16h(uint32_t* d, const uint32_t* a, uint32_t b0, uint32_t b1) {
    asm volatile("mma.sync.aligned.m16n8k16.row.col.f16.f16.f16.f16 "
        "{%0,%1},{%2,%3,%4,%5},{%6,%7},{%0,%1};"
        : "+r"(d[0]), "+r"(d[1])
        : "r"(a[0]), "r"(a[1]), "r"(a[2]), "r"(a[3]), "r"(b0), "r"(b1));
}
// f16 accum, k8 (aug chunk)
__device__ __forceinline__ void mma8h(uint32_t* d, const uint32_t* a, uint32_t b0) {
    asm volatile("mma.sync.aligned.m16n8k8.row.col.f16.f16.f16.f16 "
        "{%0,%1},{%2,%3},{%4},{%0,%1};"
        : "+r"(d[0]), "+r"(d[1])
        : "r"(a[0]), "r"(a[1]), "r"(b0));
}
__device__ __forceinline__ float tanha(float x) {
    float y; asm("tanh.approx.f32 %0,%1;" : "=f"(y) : "f"(x)); return y;
}
__device__ __forceinline__ float siga(float x) {
    return fmaf(0.5f, tanha(0.5f * x), 0.5f);
}
__device__ __forceinline__ void nbar(int id, int cnt) {
    asm volatile("bar.sync %0, %1;" :: "r"(id), "r"(cnt) : "memory");
}

// ============================================================================
// Fused PRNN. 128 samples/CTA (one wave), 512 threads, two decoupled groups
// of 64 rows. Warp (cg 0..7, grp 0..1) owns 64 rows x 16 cols, m = 4 tiles.
// All-f16 MMA accumulation; biases/xi r/z folded via aug cols 128-130 of the
// A tile (consumed by an extra m16n8k8); b1 folded into hid aug.
// ============================================================================
__global__ __launch_bounds__(THREADS, 1) void prnn_kernel(
    const float* __restrict__ x, const float* __restrict__ w_ih,
    const float* __restrict__ w_hh, const float* __restrict__ b_ih,
    const float* __restrict__ b_hh, const float* __restrict__ w1,
    const float* __restrict__ b1, const float* __restrict__ w2,
    const float* __restrict__ b2, float* __restrict__ out)
{
    extern __shared__ char sm[];
    unsigned char* sP = (unsigned char*)(sm + S_P);
    float*  sPart = (float*)(sm + S_PART);
    float4* sW2T = (float4*)(sm + S_W2T);

    const int tid = threadIdx.x;
    const int wid = tid >> 5, lane = tid & 31;
    const int rg = lane >> 2, c4 = lane & 3;
    const int cg = wid & 7, grp = wid >> 3;
    const int j0 = cg * 16;
    const int rbase = grp * 64;
    const int bBase = blockIdx.x * TPC;
    const uint32_t saB = s2u(sm + S_A0);

    // ---- stage main B-frags (8 k16 chunks), f16 ----
    for (int i = tid; i < 16384; i += THREADS) {
        int g = i & 3, ln = (i >> 2) & 31, f = (i >> 7) & 1;
        int cgs = (i >> 8) & 7, kc = i >> 11;
        int nrow = (cgs * 2 + f) * 8 + (ln >> 2);
        const float* wr = (g < 3) ? (w_hh + (g * NH + nrow) * NH) : (w1 + nrow * NH);
        wr += kc * 16 + (ln & 3) * 2;
        ((uint2*)(sm + S_BW))[i] = make_uint2(f2h2(wr[0], wr[1]), f2h2(wr[8], wr[9]));
    }
    // ---- stage aug B-frags (k8): k=0 -> w_ih[:,0], k=1 -> w_ih[:,1], k=2 -> bias ----
    for (int i = tid; i < 2048; i += THREADS) {
        int g = i & 3, ln = (i >> 2) & 31, f = (i >> 7) & 1, cgs = i >> 8;
        int nrow = (cgs * 2 + f) * 8 + (ln >> 2);
        int k0 = (ln & 3) * 2;
        float vk0 = (g < 2) ? w_ih[(g * NH + nrow) * 2] : 0.0f;
        float vk1 = (g < 2) ? w_ih[(g * NH + nrow) * 2 + 1] : 0.0f;
        float vk2 = (g == 0) ? (b_ih[nrow] + b_hh[nrow])
                  : (g == 1) ? (b_ih[NH + nrow] + b_hh[NH + nrow])
                  : (g == 2) ? b_hh[2 * NH + nrow] : b1[nrow];
        float v0 = (k0 == 0) ? vk0 : (k0 == 2) ? vk2 : 0.0f;
        float v1 = (k0 == 0) ? vk1 : 0.0f;
        ((uint32_t*)(sm + S_BAUG))[i] = f2h2(v0, v1);
    }
    for (int i = tid; i < NH; i += THREADS)
        sW2T[i] = make_float4(w2[i], w2[NH + i], w2[2 * NH + i], w2[3 * NH + i]);
    for (int i = tid; i < T_STEPS * TPC; i += THREADS) {
        int t = i >> 7, s = i & 127;
        const float* xb = x + (size_t)(bBase + s) * SEQ_L + 2 * t;
        sP[i] = (unsigned char)((xb[0] != 0.0f ? 1 : 0) | (xb[1] != 0.0f ? 2 : 0));
    }
    // zero both A buffers
    for (int i = tid; i < 2 * A_BUFSZ / 4; i += THREADS) ((uint32_t*)(sm + S_A0))[i] = 0u;
    __syncthreads();
    // buffer-0 aug: col 130 = 1.0 (d0=d1=0 for step 0)
    for (int i = tid; i < TPC; i += THREADS)
        *(uint32_t*)(sm + S_A0 + i * 272 + 260) = f2h2(1.0f, 0.0f);

    // ---- per-thread consts: xi_n pieces ----
    float baseN[4], wN0[4], wN1[4];
    #pragma unroll
    for (int ci = 0; ci < 4; ci++) {
        int col = j0 + (ci >> 1) * 8 + 2 * c4 + (ci & 1);
        baseN[ci] = b_ih[2 * NH + col];
        wN0[ci] = w_ih[(2 * NH + col) * 2];
        wN1[ci] = w_ih[(2 * NH + col) * 2 + 1];
    }
    const float b2r = b2[lane & 3];

    uint32_t hpH[4][2][2];   // h state, f16x2 per (m,f,rr)
    #pragma unroll
    for (int m = 0; m < 4; m++)
        #pragma unroll
        for (int f = 0; f < 2; f++) { hpH[m][f][0] = 0u; hpH[m][f][1] = 0u; }
    float acc = 0.0f;

    const uint32_t lm16 = saB + (uint32_t)(rbase + (lane & 15)) * 272 + (uint32_t)(lane >> 4) * 16;
    const uint32_t lm8  = saB + (uint32_t)(rbase + (lane & 15)) * 272 + 256;
    const int mybar = 1 + grp;

    __syncthreads();

    for (int t = 0; t <= T_STEPS; t++) {
        nbar(mybar, 256);   // sA[t&1] rows of this group complete

        const uint32_t abuf = (uint32_t)(t & 1) * A_BUFSZ;

        // ---------- MMA: gates (step t) + hid (step t-1), all f16 accum ----------
        uint32_t aR[4][2][2], aZ[4][2][2], aN[4][2][2], aH[4][2][2];
        #pragma unroll
        for (int m = 0; m < 4; m++)
            #pragma unroll
            for (int f = 0; f < 2; f++) {
                aR[m][f][0] = aR[m][f][1] = 0u;
                aZ[m][f][0] = aZ[m][f][1] = 0u;
                aN[m][f][0] = aN[m][f][1] = 0u;
                aH[m][f][0] = aH[m][f][1] = 0u;
            }
        #pragma unroll
        for (int kc = 0; kc < 8; kc++) {
            uint32_t A[4][4];
            #pragma unroll
            for (int m = 0; m < 4; m++) ldm4(A[m], lm16 + abuf + m * 16 * 272 + kc * 32);
            #pragma unroll
            for (int f = 0; f < 2; f++) {
                const uint4* bp = (const uint4*)(sm + S_BW +
                    ((size_t)(((kc * 8 + cg) * 2 + f) * 32 + lane)) * 32);
                uint4 B01 = bp[0];
                uint4 B23 = bp[1];
                if (t < T_STEPS) {
                    #pragma unroll
                    for (int m = 0; m < 4; m++) {
                        mma16h(aR[m][f], A[m], B01.x, B01.y);
                        mma16h(aZ[m][f], A[m], B01.z, B01.w);
                        mma16h(aN[m][f], A[m], B23.x, B23.y);
                    }
                }
                if (t >= 1) {
                    #pragma unroll
                    for (int m = 0; m < 4; m++) mma16h(aH[m][f], A[m], B23.z, B23.w);
                }
            }
        }
        // aug k8 chunk (xi r/z, biases, b1)
        {
            uint32_t A8[4][2];
            #pragma unroll
            for (int m = 0; m < 4; m++) ldm2(A8[m], lm8 + abuf + m * 16 * 272);
            #pragma unroll
            for (int f = 0; f < 2; f++) {
                uint4 BA = *(const uint4*)(sm + S_BAUG +
                    ((size_t)((cg * 2 + f) * 32 + lane)) * 16);
                if (t < T_STEPS) {
                    #pragma unroll
                    for (int m = 0; m < 4; m++) {
                        mma8h(aR[m][f], A8[m], BA.x);
                        mma8h(aZ[m][f], A8[m], BA.y);
                        mma8h(aN[m][f], A8[m], BA.z);
                    }
                }
                if (t >= 1) {
                    #pragma unroll
                    for (int m = 0; m < 4; m++) mma8h(aH[m][f], A8[m], BA.w);
                }
            }
        }

        // ---------- gate epilogue: h_t -> sA[(t+1)&1] (+ aug d_{t+1}) ----------
        if (t < T_STEPS) {
            const uint32_t wbuf = (uint32_t)((t + 1) & 1) * A_BUFSZ;
            #pragma unroll
            for (int m = 0; m < 4; m++)
                #pragma unroll
                for (int rr = 0; rr < 2; rr++) {
                    int row = rbase + m * 16 + rg + rr * 8;
                    int v = (t > 0) ? sP[(t - 1) * TPC + row] : 0;
                    if (cg == 0 && c4 == 0) {
                        int vn = sP[t * TPC + row];
                        *(uint2*)(sm + S_A0 + wbuf + row * 272 + 256) =
                            make_uint2(f2h2((float)(vn & 1), (float)(vn >> 1)), f2h2(1.0f, 0.0f));
                    }
                    #pragma unroll
                    for (int f = 0; f < 2; f++) {
                        float2 vR = h22f2(aR[m][f][rr]);
                        float2 vZ = h22f2(aZ[m][f][rr]);
                        float2 vN = h22f2(aN[m][f][rr]);
                        float2 hv = h22f2(hpH[m][f][rr]);
                        float hh[2];
                        #pragma unroll
                        for (int lo = 0; lo < 2; lo++) {
                            int ci = f * 2 + lo;
                            float gr = lo ? vR.y : vR.x;
                            float gz = lo ? vZ.y : vZ.x;
                            float gn = lo ? vN.y : vN.x;
                            float hprev = lo ? hv.y : hv.x;
                            float xn = baseN[ci];
                            if (v & 1) xn += wN0[ci];
                            if (v & 2) xn += wN1[ci];
                            float r = siga(gr);
                            float z = siga(gz);
                            float n = tanha(xn + r * gn);
                            hh[lo] = n + z * (hprev - n);
                        }
                        uint32_t hu = f2h2(hh[0], hh[1]);
                        hpH[m][f][rr] = hu;
                        int col0 = j0 + f * 8 + 2 * c4;
                        *(uint32_t*)(sm + S_A0 + wbuf + row * 272 + col0 * 2) = hu;
                    }
                }
        }

        // ---------- head partials for step t-1 -> sPart ----------
        if (t >= 1) {
            float4 wci[4];
            #pragma unroll
            for (int ci = 0; ci < 4; ci++)
                wci[ci] = sW2T[j0 + (ci >> 1) * 8 + 2 * c4 + (ci & 1)];
            float p[8][4];
            #pragma unroll
            for (int q = 0; q < 8; q++)
                #pragma unroll
                for (int o = 0; o < 4; o++) p[q][o] = 0.0f;
            #pragma unroll
            for (int m = 0; m < 4; m++)
                #pragma unroll
                for (int f = 0; f < 2; f++)
                    #pragma unroll
                    for (int rr = 0; rr < 2; rr++) {
                        float2 hvv = h22f2(aH[m][f][rr]);
                        int q = m * 2 + rr;
                        #pragma unroll
                        for (int lo = 0; lo < 2; lo++) {
                            int ci = f * 2 + lo;
                            float hid = fmaxf(lo ? hvv.y : hvv.x, 0.0f);  // b1 folded in aug
                            p[q][0] = fmaf(hid, wci[ci].x, p[q][0]);
                            p[q][1] = fmaf(hid, wci[ci].y, p[q][1]);
                            p[q][2] = fmaf(hid, wci[ci].z, p[q][2]);
                            p[q][3] = fmaf(hid, wci[ci].w, p[q][3]);
                        }
                    }
            #pragma unroll
            for (int q = 0; q < 8; q++)
                #pragma unroll
                for (int o = 0; o < 4; o++) {
                    float v = p[q][o];
                    v += __shfl_xor_sync(0xffffffffu, v, 1);
                    v += __shfl_xor_sync(0xffffffffu, v, 2);
                    p[q][o] = v;
                }
            if (c4 == 0) {
                float4* dst = (float4*)(sPart + cg * 512);
                #pragma unroll
                for (int q = 0; q < 8; q++) {
                    int row = rbase + (q >> 1) * 16 + rg + (q & 1) * 8;
                    dst[row] = make_float4(p[q][0], p[q][1], p[q][2], p[q][3]);
                }
            }
        }

        nbar(mybar, 256);   // sPart rows of this group complete

        // ---------- logits + logsumexp for step t-1 ----------
        if (t >= 1) {
            int row = rbase + cg * 8 + (lane >> 2);
            const float* pb = sPart + row * 4 + (lane & 3);
            float l = b2r;
            #pragma unroll
            for (int w = 0; w < 8; w++) l += pb[w * 512];
            float m1 = fmaxf(l, __shfl_xor_sync(0xffffffffu, l, 1));
            float mx = fmaxf(m1, __shfl_xor_sync(0xffffffffu, m1, 2));
            float e = __expf(l - mx);
            float s = e + __shfl_xor_sync(0xffffffffu, e, 1);
            s += __shfl_xor_sync(0xffffffffu, s, 2);
            float lse = mx + __logf(s);
            int idx = sP[(t - 1) * TPC + row];
            float lpick = __shfl_sync(0xffffffffu, l, (lane & ~3) | idx);
            if ((lane & 3) == 0) acc += lpick - lse;
        }
    }

    if ((lane & 3) == 0)
        out[bBase + rbase + cg * 8 + (lane >> 2)] = acc;
}

extern "C" void kernel_launch(void* const* d_in, const int* in_sizes, int n_in,
                              void* d_out, int out_size) {
    const float* x    = (const float*)d_in[0];
    const float* w_ih = (const float*)d_in[1];
    const float* w_hh = (const float*)d_in[2];
    const float* b_ih = (const float*)d_in[3];
    const float* b_hh = (const float*)d_in[4];
    const float* w1   = (const float*)d_in[5];
    const float* b1   = (const float*)d_in[6];
    const float* w2   = (const float*)d_in[7];
    const float* b2   = (const float*)d_in[8];
    float* out = (float*)d_out;

    cudaFuncSetAttribute(prnn_kernel, cudaFuncAttributeMaxDynamicSharedMemorySize, SMEM_TOTAL);
    prnn_kernel<<<NCTA, THREADS, SMEM_TOTAL>>>(
        x, w_ih, w_hh, b_ih, b_hh, w1, b1, w2, b2, out);
}

// round 16
// speedup vs baseline: 1.3747x; 1.0348x over previous
#include <cuda_runtime.h>
#include <cuda_fp16.h>
#include <cstdint>

#define BATCH   16384
#define SEQ_L   64
#define T_STEPS 32
#define NH      128
#define TPC     128
#define NCTA    (BATCH / TPC)   // 128 -> exactly one wave
#define THREADS 512

// ---------------- smem layout (bytes) ----------------
#define S_BW    0                // main B-frags [8kc][8cg][2f][32lane][4g] uint2 = 131072
#define S_BAUG  131072           // aug  B-frags [8cg][2f][32lane][4g] uint32     = 8192
#define S_A0    139264           // A tile parity 0: [128 rows][272B] f16
#define S_A1    174080           // A tile parity 1                               = 34816
#define S_P     208896           // uint8 patch idx [32][128]                     = 4096
#define S_PART  212992           // f32 partials [8 cg][128 row][4 o]             = 16384
#define S_W2T   229376           // float4 w2T [128 col][4 o]                     = 2048
#define SMEM_TOTAL 231424
#define A_BUFSZ 34816

// ---------------- helpers ----------------
__device__ __forceinline__ uint32_t s2u(const void* p) {
    uint32_t a;
    asm("{ .reg .u64 t; cvta.to.shared.u64 t, %1; cvt.u32.u64 %0, t; }" : "=r"(a) : "l"(p));
    return a;
}
__device__ __forceinline__ uint32_t f2h2(float lo, float hi) {
    __half2 h = __floats2half2_rn(lo, hi);
    return *(uint32_t*)&h;
}
__device__ __forceinline__ __half2 u2h2(uint32_t u) { return *(__half2*)&u; }
__device__ __forceinline__ uint32_t h22u(__half2 h) { return *(uint32_t*)&h; }
__device__ __forceinline__ float2 h22f2(uint32_t u) {
    return __half22float2(*(__half2*)&u);
}
__device__ __forceinline__ void ldm4(uint32_t* a, uint32_t addr) {
    asm volatile("ldmatrix.sync.aligned.m8n8.x4.shared.b16 {%0,%1,%2,%3}, [%4];"
        : "=r"(a[0]), "=r"(a[1]), "=r"(a[2]), "=r"(a[3]) : "r"(addr));
}
__device__ __forceinline__ void ldm2(uint32_t* a, uint32_t addr) {
    asm volatile("ldmatrix.sync.aligned.m8n8.x2.shared.b16 {%0,%1}, [%2];"
        : "=r"(a[0]), "=r"(a[1]) : "r"(addr));
}
__device__ __forceinline__ void mma16h(uint32_t* d, const uint32_t* a, uint32_t b0, uint32_t b1) {
    asm volatile("mma.sync.aligned.m16n8k16.row.col.f16.f16.f16.f16 "
        "{%0,%1},{%2,%3,%4,%5},{%6,%7},{%0,%1};"
        : "+r"(d[0]), "+r"(d[1])
        : "r"(a[0]), "r"(a[1]), "r"(a[2]), "r"(a[3]), "r"(b0), "r"(b1));
}
__device__ __forceinline__ void mma8h(uint32_t* d, const uint32_t* a, uint32_t b0) {
    asm volatile("mma.sync.aligned.m16n8k8.row.col.f16.f16.f16.f16 "
        "{%0,%1},{%2,%3},{%4},{%0,%1};"
        : "+r"(d[0]), "+r"(d[1])
        : "r"(a[0]), "r"(a[1]), "r"(b0));
}
// packed half2 tanh (sm_75+)
__device__ __forceinline__ __half2 tanh2h(__half2 x) {
    uint32_t y, xi = h22u(x);
    asm("tanh.approx.f16x2 %0,%1;" : "=r"(y) : "r"(xi));
    return u2h2(y);
}
__device__ __forceinline__ void nbar(int id, int cnt) {
    asm volatile("bar.sync %0, %1;" :: "r"(id), "r"(cnt) : "memory");
}

// ============================================================================
// Fused PRNN. 128 samples/CTA (one wave), 512 threads, two decoupled groups
// of 64 rows. Warp (cg, grp) owns 64 rows x 16 cols. All-f16 MMA accum;
// biases/xi r/z folded via aug A cols 128-130 + m16n8k8; b1 folded in hid aug.
// NEW: entire gate epilogue in packed half2 (tanh.approx.f16x2) -> MUFU and
// epilogue ALU roughly halved.
// ============================================================================
__global__ __launch_bounds__(THREADS, 1) void prnn_kernel(
    const float* __restrict__ x, const float* __restrict__ w_ih,
    const float* __restrict__ w_hh, const float* __restrict__ b_ih,
    const float* __restrict__ b_hh, const float* __restrict__ w1,
    const float* __restrict__ b1, const float* __restrict__ w2,
    const float* __restrict__ b2, float* __restrict__ out)
{
    extern __shared__ char sm[];
    unsigned char* sP = (unsigned char*)(sm + S_P);
    float*  sPart = (float*)(sm + S_PART);
    float4* sW2T = (float4*)(sm + S_W2T);

    const int tid = threadIdx.x;
    const int wid = tid >> 5, lane = tid & 31;
    const int rg = lane >> 2, c4 = lane & 3;
    const int cg = wid & 7, grp = wid >> 3;
    const int j0 = cg * 16;
    const int rbase = grp * 64;
    const int bBase = blockIdx.x * TPC;
    const uint32_t saB = s2u(sm + S_A0);

    // ---- stage main B-frags (8 k16 chunks), f16 ----
    for (int i = tid; i < 16384; i += THREADS) {
        int g = i & 3, ln = (i >> 2) & 31, f = (i >> 7) & 1;
        int cgs = (i >> 8) & 7, kc = i >> 11;
        int nrow = (cgs * 2 + f) * 8 + (ln >> 2);
        const float* wr = (g < 3) ? (w_hh + (g * NH + nrow) * NH) : (w1 + nrow * NH);
        wr += kc * 16 + (ln & 3) * 2;
        ((uint2*)(sm + S_BW))[i] = make_uint2(f2h2(wr[0], wr[1]), f2h2(wr[8], wr[9]));
    }
    // ---- stage aug B-frags (k8): k=0 -> w_ih[:,0], k=1 -> w_ih[:,1], k=2 -> bias ----
    for (int i = tid; i < 2048; i += THREADS) {
        int g = i & 3, ln = (i >> 2) & 31, f = (i >> 7) & 1, cgs = i >> 8;
        int nrow = (cgs * 2 + f) * 8 + (ln >> 2);
        int k0 = (ln & 3) * 2;
        float vk0 = (g < 2) ? w_ih[(g * NH + nrow) * 2] : 0.0f;
        float vk1 = (g < 2) ? w_ih[(g * NH + nrow) * 2 + 1] : 0.0f;
        float vk2 = (g == 0) ? (b_ih[nrow] + b_hh[nrow])
                  : (g == 1) ? (b_ih[NH + nrow] + b_hh[NH + nrow])
                  : (g == 2) ? b_hh[2 * NH + nrow] : b1[nrow];
        float v0 = (k0 == 0) ? vk0 : (k0 == 2) ? vk2 : 0.0f;
        float v1 = (k0 == 0) ? vk1 : 0.0f;
        ((uint32_t*)(sm + S_BAUG))[i] = f2h2(v0, v1);
    }
    for (int i = tid; i < NH; i += THREADS)
        sW2T[i] = make_float4(w2[i], w2[NH + i], w2[2 * NH + i], w2[3 * NH + i]);
    for (int i = tid; i < T_STEPS * TPC; i += THREADS) {
        int t = i >> 7, s = i & 127;
        const float* xb = x + (size_t)(bBase + s) * SEQ_L + 2 * t;
        sP[i] = (unsigned char)((xb[0] != 0.0f ? 1 : 0) | (xb[1] != 0.0f ? 2 : 0));
    }
    for (int i = tid; i < 2 * A_BUFSZ / 4; i += THREADS) ((uint32_t*)(sm + S_A0))[i] = 0u;
    __syncthreads();
    for (int i = tid; i < TPC; i += THREADS)
        *(uint32_t*)(sm + S_A0 + i * 272 + 260) = f2h2(1.0f, 0.0f);

    // ---- per-thread consts: xi_n pieces as packed half2 per f ----
    __half2 baseN2[2], wN02[2], wN12[2];
    #pragma unroll
    for (int f = 0; f < 2; f++) {
        int col = j0 + f * 8 + 2 * c4;      // lo pair (col, col+1)
        baseN2[f] = __floats2half2_rn(b_ih[2 * NH + col], b_ih[2 * NH + col + 1]);
        wN02[f]   = __floats2half2_rn(w_ih[(2 * NH + col) * 2], w_ih[(2 * NH + col + 1) * 2]);
        wN12[f]   = __floats2half2_rn(w_ih[(2 * NH + col) * 2 + 1], w_ih[(2 * NH + col + 1) * 2 + 1]);
    }
    const float b2r = b2[lane & 3];
    const __half2 h05 = __floats2half2_rn(0.5f, 0.5f);

    uint32_t hpH[4][2][2];
    #pragma unroll
    for (int m = 0; m < 4; m++)
        #pragma unroll
        for (int f = 0; f < 2; f++) { hpH[m][f][0] = 0u; hpH[m][f][1] = 0u; }
    float acc = 0.0f;

    const uint32_t lm16 = saB + (uint32_t)(rbase + (lane & 15)) * 272 + (uint32_t)(lane >> 4) * 16;
    const uint32_t lm8  = saB + (uint32_t)(rbase + (lane & 15)) * 272 + 256;
    const int mybar = 1 + grp;

    __syncthreads();

    for (int t = 0; t <= T_STEPS; t++) {
        nbar(mybar, 256);

        const uint32_t abuf = (uint32_t)(t & 1) * A_BUFSZ;

        // ---------- MMA: gates (step t) + hid (step t-1), all f16 accum ----------
        uint32_t aR[4][2][2], aZ[4][2][2], aN[4][2][2], aH[4][2][2];
        #pragma unroll
        for (int m = 0; m < 4; m++)
            #pragma unroll
            for (int f = 0; f < 2; f++) {
                aR[m][f][0] = aR[m][f][1] = 0u;
                aZ[m][f][0] = aZ[m][f][1] = 0u;
                aN[m][f][0] = aN[m][f][1] = 0u;
                aH[m][f][0] = aH[m][f][1] = 0u;
            }
        #pragma unroll
        for (int kc = 0; kc < 8; kc++) {
            uint32_t A[4][4];
            #pragma unroll
            for (int m = 0; m < 4; m++) ldm4(A[m], lm16 + abuf + m * 16 * 272 + kc * 32);
            #pragma unroll
            for (int f = 0; f < 2; f++) {
                const uint4* bp = (const uint4*)(sm + S_BW +
                    ((size_t)(((kc * 8 + cg) * 2 + f) * 32 + lane)) * 32);
                uint4 B01 = bp[0];
                uint4 B23 = bp[1];
                if (t < T_STEPS) {
                    #pragma unroll
                    for (int m = 0; m < 4; m++) {
                        mma16h(aR[m][f], A[m], B01.x, B01.y);
                        mma16h(aZ[m][f], A[m], B01.z, B01.w);
                        mma16h(aN[m][f], A[m], B23.x, B23.y);
                    }
                }
                if (t >= 1) {
                    #pragma unroll
                    for (int m = 0; m < 4; m++) mma16h(aH[m][f], A[m], B23.z, B23.w);
                }
            }
        }
        {
            uint32_t A8[4][2];
            #pragma unroll
            for (int m = 0; m < 4; m++) ldm2(A8[m], lm8 + abuf + m * 16 * 272);
            #pragma unroll
            for (int f = 0; f < 2; f++) {
                uint4 BA = *(const uint4*)(sm + S_BAUG +
                    ((size_t)((cg * 2 + f) * 32 + lane)) * 16);
                if (t < T_STEPS) {
                    #pragma unroll
                    for (int m = 0; m < 4; m++) {
                        mma8h(aR[m][f], A8[m], BA.x);
                        mma8h(aZ[m][f], A8[m], BA.y);
                        mma8h(aN[m][f], A8[m], BA.z);
                    }
                }
                if (t >= 1) {
                    #pragma unroll
                    for (int m = 0; m < 4; m++) mma8h(aH[m][f], A8[m], BA.w);
                }
            }
        }

        // ---------- gate epilogue (packed half2): h_t -> sA[(t+1)&1] ----------
        if (t < T_STEPS) {
            const uint32_t wbuf = (uint32_t)((t + 1) & 1) * A_BUFSZ;
            #pragma unroll
            for (int m = 0; m < 4; m++)
                #pragma unroll
                for (int rr = 0; rr < 2; rr++) {
                    int row = rbase + m * 16 + rg + rr * 8;
                    int v = (t > 0) ? sP[(t - 1) * TPC + row] : 0;
                    if (cg == 0 && c4 == 0) {
                        int vn = sP[t * TPC + row];
                        *(uint2*)(sm + S_A0 + wbuf + row * 272 + 256) =
                            make_uint2(f2h2((float)(vn & 1), (float)(vn >> 1)), f2h2(1.0f, 0.0f));
                    }
                    #pragma unroll
                    for (int f = 0; f < 2; f++) {
                        __half2 xn = baseN2[f];
                        if (v & 1) xn = __hadd2(xn, wN02[f]);
                        if (v & 2) xn = __hadd2(xn, wN12[f]);
                        __half2 r = __hfma2(tanh2h(__hmul2(u2h2(aR[m][f][rr]), h05)), h05, h05);
                        __half2 z = __hfma2(tanh2h(__hmul2(u2h2(aZ[m][f][rr]), h05)), h05, h05);
                        __half2 n = tanh2h(__hfma2(r, u2h2(aN[m][f][rr]), xn));
                        __half2 hprev = u2h2(hpH[m][f][rr]);
                        __half2 h = __hfma2(z, __hsub2(hprev, n), n);
                        uint32_t hu = h22u(h);
                        hpH[m][f][rr] = hu;
                        int col0 = j0 + f * 8 + 2 * c4;
                        *(uint32_t*)(sm + S_A0 + wbuf + row * 272 + col0 * 2) = hu;
                    }
                }
        }

        // ---------- head partials for step t-1 -> sPart ----------
        if (t >= 1) {
            float4 wci[4];
            #pragma unroll
            for (int ci = 0; ci < 4; ci++)
                wci[ci] = sW2T[j0 + (ci >> 1) * 8 + 2 * c4 + (ci & 1)];
            float p[8][4];
            #pragma unroll
            for (int q = 0; q < 8; q++)
                #pragma unroll
                for (int o = 0; o < 4; o++) p[q][o] = 0.0f;
            #pragma unroll
            for (int m = 0; m < 4; m++)
                #pragma unroll
                for (int f = 0; f < 2; f++)
                    #pragma unroll
                    for (int rr = 0; rr < 2; rr++) {
                        float2 hvv = h22f2(aH[m][f][rr]);
                        int q = m * 2 + rr;
                        #pragma unroll
                        for (int lo = 0; lo < 2; lo++) {
                            int ci = f * 2 + lo;
                            float hid = fmaxf(lo ? hvv.y : hvv.x, 0.0f);
                            p[q][0] = fmaf(hid, wci[ci].x, p[q][0]);
                            p[q][1] = fmaf(hid, wci[ci].y, p[q][1]);
                            p[q][2] = fmaf(hid, wci[ci].z, p[q][2]);
                            p[q][3] = fmaf(hid, wci[ci].w, p[q][3]);
                        }
                    }
            #pragma unroll
            for (int q = 0; q < 8; q++)
                #pragma unroll
                for (int o = 0; o < 4; o++) {
                    float v = p[q][o];
                    v += __shfl_xor_sync(0xffffffffu, v, 1);
                    v += __shfl_xor_sync(0xffffffffu, v, 2);
                    p[q][o] = v;
                }
            if (c4 == 0) {
                float4* dst = (float4*)(sPart + cg * 512);
                #pragma unroll
                for (int q = 0; q < 8; q++) {
                    int row = rbase + (q >> 1) * 16 + rg + (q & 1) * 8;
                    dst[row] = make_float4(p[q][0], p[q][1], p[q][2], p[q][3]);
                }
            }
        }

        nbar(mybar, 256);

        // ---------- logits + logsumexp for step t-1 ----------
        if (t >= 1) {
            int row = rbase + cg * 8 + (lane >> 2);
            const float* pb = sPart + row * 4 + (lane & 3);
            float l = b2r;
            #pragma unroll
            for (int w = 0; w < 8; w++) l += pb[w * 512];
            float m1 = fmaxf(l, __shfl_xor_sync(0xffffffffu, l, 1));
            float mx = fmaxf(m1, __shfl_xor_sync(0xffffffffu, m1, 2));
            float e = __expf(l - mx);
            float s = e + __shfl_xor_sync(0xffffffffu, e, 1);
            s += __shfl_xor_sync(0xffffffffu, s, 2);
            float lse = mx + __logf(s);
            int idx = sP[(t - 1) * TPC + row];
            float lpick = __shfl_sync(0xffffffffu, l, (lane & ~3) | idx);
            if ((lane & 3) == 0) acc += lpick - lse;
        }
    }

    if ((lane & 3) == 0)
        out[bBase + rbase + cg * 8 + (lane >> 2)] = acc;
}

extern "C" void kernel_launch(void* const* d_in, const int* in_sizes, int n_in,
                              void* d_out, int out_size) {
    const float* x    = (const float*)d_in[0];
    const float* w_ih = (const float*)d_in[1];
    const float* w_hh = (const float*)d_in[2];
    const float* b_ih = (const float*)d_in[3];
    const float* b_hh = (const float*)d_in[4];
    const float* w1   = (const float*)d_in[5];
    const float* b1   = (const float*)d_in[6];
    const float* w2   = (const float*)d_in[7];
    const float* b2   = (const float*)d_in[8];
    float* out = (float*)d_out;

    cudaFuncSetAttribute(prnn_kernel, cudaFuncAttributeMaxDynamicSharedMemorySize, SMEM_TOTAL);
    prnn_kernel<<<NCTA, THREADS, SMEM_TOTAL>>>(
        x, w_ih, w_hh, b_ih, b_hh, w1, b1, w2, b2, out);
}

// round 17
// speedup vs baseline: 1.4393x; 1.0470x over previous
#include <cuda_runtime.h>
#include <cuda_fp16.h>
#include <cstdint>

#define BATCH   16384
#define SEQ_L   64
#define T_STEPS 32
#define NH      128
#define TPC     128
#define NCTA    (BATCH / TPC)   // 128 -> exactly one wave
#define THREADS 512

// ---------------- smem layout (bytes) ----------------
#define S_BW    0                // main B-frags [8kc][8cg][2f][32lane][4g] uint2 = 131072
#define S_BAUG  131072           // aug  B-frags [8cg][2f][32lane][4g] uint32     = 8192
#define S_A0    139264           // A tile parity 0: [128 rows][272B] f16
#define S_A1    174080           // A tile parity 1                               = 34816
#define S_P     208896           // uint8 patch idx [32][128]                     = 4096
#define S_PART  212992           // f16x2 partials [2 par][8 cg][128 row] uint2   = 16384
#define S_W2T   229376           // float4 w2T [128 col][4 o]                     = 2048
#define SMEM_TOTAL 231424
#define A_BUFSZ 34816

// ---------------- helpers ----------------
__device__ __forceinline__ uint32_t s2u(const void* p) {
    uint32_t a;
    asm("{ .reg .u64 t; cvta.to.shared.u64 t, %1; cvt.u32.u64 %0, t; }" : "=r"(a) : "l"(p));
    return a;
}
__device__ __forceinline__ uint32_t f2h2(float lo, float hi) {
    __half2 h = __floats2half2_rn(lo, hi);
    return *(uint32_t*)&h;
}
__device__ __forceinline__ __half2 u2h2(uint32_t u) { return *(__half2*)&u; }
__device__ __forceinline__ uint32_t h22u(__half2 h) { return *(uint32_t*)&h; }
__device__ __forceinline__ float2 h22f2(uint32_t u) {
    return __half22float2(*(__half2*)&u);
}
__device__ __forceinline__ void ldm4(uint32_t* a, uint32_t addr) {
    asm volatile("ldmatrix.sync.aligned.m8n8.x4.shared.b16 {%0,%1,%2,%3}, [%4];"
        : "=r"(a[0]), "=r"(a[1]), "=r"(a[2]), "=r"(a[3]) : "r"(addr));
}
__device__ __forceinline__ void ldm2(uint32_t* a, uint32_t addr) {
    asm volatile("ldmatrix.sync.aligned.m8n8.x2.shared.b16 {%0,%1}, [%2];"
        : "=r"(a[0]), "=r"(a[1]) : "r"(addr));
}
__device__ __forceinline__ void mma16h(uint32_t* d, const uint32_t* a, uint32_t b0, uint32_t b1) {
    asm volatile("mma.sync.aligned.m16n8k16.row.col.f16.f16.f16.f16 "
        "{%0,%1},{%2,%3,%4,%5},{%6,%7},{%0,%1};"
        : "+r"(d[0]), "+r"(d[1])
        : "r"(a[0]), "r"(a[1]), "r"(a[2]), "r"(a[3]), "r"(b0), "r"(b1));
}
__device__ __forceinline__ void mma8h(uint32_t* d, const uint32_t* a, uint32_t b0) {
    asm volatile("mma.sync.aligned.m16n8k8.row.col.f16.f16.f16.f16 "
        "{%0,%1},{%2,%3},{%4},{%0,%1};"
        : "+r"(d[0]), "+r"(d[1])
        : "r"(a[0]), "r"(a[1]), "r"(b0));
}
__device__ __forceinline__ __half2 tanh2h(__half2 x) {
    uint32_t y, xi = h22u(x);
    asm("tanh.approx.f16x2 %0,%1;" : "=r"(y) : "r"(xi));
    return u2h2(y);
}
__device__ __forceinline__ void nbar(int id, int cnt) {
    asm volatile("bar.sync %0, %1;" :: "r"(id), "r"(cnt) : "memory");
}

// ============================================================================
// Fused PRNN. 128 samples/CTA (one wave), 512 threads, two decoupled groups
// of 64 rows. All-f16 MMA accum; biases/xi folded via aug cols + m16n8k8.
// ONE barrier/iter: sPart double-buffered (f16x2); lse for step t-2 runs
// under the MMA latency shadow (R13-proven skewed pipeline).
// ============================================================================
__global__ __launch_bounds__(THREADS, 1) void prnn_kernel(
    const float* __restrict__ x, const float* __restrict__ w_ih,
    const float* __restrict__ w_hh, const float* __restrict__ b_ih,
    const float* __restrict__ b_hh, const float* __restrict__ w1,
    const float* __restrict__ b1, const float* __restrict__ w2,
    const float* __restrict__ b2, float* __restrict__ out)
{
    extern __shared__ char sm[];
    unsigned char* sP = (unsigned char*)(sm + S_P);
    float4* sW2T = (float4*)(sm + S_W2T);

    const int tid = threadIdx.x;
    const int wid = tid >> 5, lane = tid & 31;
    const int rg = lane >> 2, c4 = lane & 3;
    const int cg = wid & 7, grp = wid >> 3;
    const int j0 = cg * 16;
    const int rbase = grp * 64;
    const int bBase = blockIdx.x * TPC;
    const uint32_t saB = s2u(sm + S_A0);

    // ---- stage main B-frags (8 k16 chunks), f16 ----
    for (int i = tid; i < 16384; i += THREADS) {
        int g = i & 3, ln = (i >> 2) & 31, f = (i >> 7) & 1;
        int cgs = (i >> 8) & 7, kc = i >> 11;
        int nrow = (cgs * 2 + f) * 8 + (ln >> 2);
        const float* wr = (g < 3) ? (w_hh + (g * NH + nrow) * NH) : (w1 + nrow * NH);
        wr += kc * 16 + (ln & 3) * 2;
        ((uint2*)(sm + S_BW))[i] = make_uint2(f2h2(wr[0], wr[1]), f2h2(wr[8], wr[9]));
    }
    // ---- stage aug B-frags (k8) ----
    for (int i = tid; i < 2048; i += THREADS) {
        int g = i & 3, ln = (i >> 2) & 31, f = (i >> 7) & 1, cgs = i >> 8;
        int nrow = (cgs * 2 + f) * 8 + (ln >> 2);
        int k0 = (ln & 3) * 2;
        float vk0 = (g < 2) ? w_ih[(g * NH + nrow) * 2] : 0.0f;
        float vk1 = (g < 2) ? w_ih[(g * NH + nrow) * 2 + 1] : 0.0f;
        float vk2 = (g == 0) ? (b_ih[nrow] + b_hh[nrow])
                  : (g == 1) ? (b_ih[NH + nrow] + b_hh[NH + nrow])
                  : (g == 2) ? b_hh[2 * NH + nrow] : b1[nrow];
        float v0 = (k0 == 0) ? vk0 : (k0 == 2) ? vk2 : 0.0f;
        float v1 = (k0 == 0) ? vk1 : 0.0f;
        ((uint32_t*)(sm + S_BAUG))[i] = f2h2(v0, v1);
    }
    for (int i = tid; i < NH; i += THREADS)
        sW2T[i] = make_float4(w2[i], w2[NH + i], w2[2 * NH + i], w2[3 * NH + i]);
    for (int i = tid; i < T_STEPS * TPC; i += THREADS) {
        int t = i >> 7, s = i & 127;
        const float* xb = x + (size_t)(bBase + s) * SEQ_L + 2 * t;
        sP[i] = (unsigned char)((xb[0] != 0.0f ? 1 : 0) | (xb[1] != 0.0f ? 2 : 0));
    }
    for (int i = tid; i < 2 * A_BUFSZ / 4; i += THREADS) ((uint32_t*)(sm + S_A0))[i] = 0u;
    __syncthreads();
    for (int i = tid; i < TPC; i += THREADS)
        *(uint32_t*)(sm + S_A0 + i * 272 + 260) = f2h2(1.0f, 0.0f);

    // ---- per-thread consts: xi_n pieces (packed half2) ----
    __half2 baseN2[2], wN02[2], wN12[2];
    #pragma unroll
    for (int f = 0; f < 2; f++) {
        int col = j0 + f * 8 + 2 * c4;
        baseN2[f] = __floats2half2_rn(b_ih[2 * NH + col], b_ih[2 * NH + col + 1]);
        wN02[f]   = __floats2half2_rn(w_ih[(2 * NH + col) * 2], w_ih[(2 * NH + col + 1) * 2]);
        wN12[f]   = __floats2half2_rn(w_ih[(2 * NH + col) * 2 + 1], w_ih[(2 * NH + col + 1) * 2 + 1]);
    }
    const float b2r = b2[lane & 3];
    const __half2 h05 = __floats2half2_rn(0.5f, 0.5f);

    uint32_t hpH[4][2][2];
    #pragma unroll
    for (int m = 0; m < 4; m++)
        #pragma unroll
        for (int f = 0; f < 2; f++) { hpH[m][f][0] = 0u; hpH[m][f][1] = 0u; }
    float acc = 0.0f;

    const uint32_t lm16 = saB + (uint32_t)(rbase + (lane & 15)) * 272 + (uint32_t)(lane >> 4) * 16;
    const uint32_t lm8  = saB + (uint32_t)(rbase + (lane & 15)) * 272 + 256;
    const int mybar = 1 + grp;

    __syncthreads();

    for (int t = 0; t <= T_STEPS + 1; t++) {
        nbar(mybar, 256);   // sA[t&1] + sPart[(t-1)&1] rows of this group done

        const uint32_t abuf = (uint32_t)(t & 1) * A_BUFSZ;

        // ---------- MMA: gates (step t) + hid (step t-1), all f16 accum ----------
        uint32_t aR[4][2][2], aZ[4][2][2], aN[4][2][2], aH[4][2][2];
        #pragma unroll
        for (int m = 0; m < 4; m++)
            #pragma unroll
            for (int f = 0; f < 2; f++) {
                aR[m][f][0] = aR[m][f][1] = 0u;
                aZ[m][f][0] = aZ[m][f][1] = 0u;
                aN[m][f][0] = aN[m][f][1] = 0u;
                aH[m][f][0] = aH[m][f][1] = 0u;
            }
        if (t <= T_STEPS) {
            #pragma unroll
            for (int kc = 0; kc < 8; kc++) {
                uint32_t A[4][4];
                #pragma unroll
                for (int m = 0; m < 4; m++) ldm4(A[m], lm16 + abuf + m * 16 * 272 + kc * 32);
                #pragma unroll
                for (int f = 0; f < 2; f++) {
                    const uint4* bp = (const uint4*)(sm + S_BW +
                        ((size_t)(((kc * 8 + cg) * 2 + f) * 32 + lane)) * 32);
                    uint4 B01 = bp[0];
                    uint4 B23 = bp[1];
                    if (t < T_STEPS) {
                        #pragma unroll
                        for (int m = 0; m < 4; m++) {
                            mma16h(aR[m][f], A[m], B01.x, B01.y);
                            mma16h(aZ[m][f], A[m], B01.z, B01.w);
                            mma16h(aN[m][f], A[m], B23.x, B23.y);
                        }
                    }
                    if (t >= 1) {
                        #pragma unroll
                        for (int m = 0; m < 4; m++) mma16h(aH[m][f], A[m], B23.z, B23.w);
                    }
                }
            }
            uint32_t A8[4][2];
            #pragma unroll
            for (int m = 0; m < 4; m++) ldm2(A8[m], lm8 + abuf + m * 16 * 272);
            #pragma unroll
            for (int f = 0; f < 2; f++) {
                uint4 BA = *(const uint4*)(sm + S_BAUG +
                    ((size_t)((cg * 2 + f) * 32 + lane)) * 16);
                if (t < T_STEPS) {
                    #pragma unroll
                    for (int m = 0; m < 4; m++) {
                        mma8h(aR[m][f], A8[m], BA.x);
                        mma8h(aZ[m][f], A8[m], BA.y);
                        mma8h(aN[m][f], A8[m], BA.z);
                    }
                }
                if (t >= 1) {
                    #pragma unroll
                    for (int m = 0; m < 4; m++) mma8h(aH[m][f], A8[m], BA.w);
                }
            }
        }

        // ---------- logits + logsumexp for step t-2 (under MMA shadow) ----------
        if (t >= 2) {
            int row = rbase + cg * 8 + (lane >> 2);
            int o = lane & 3;
            const char* pb = sm + S_PART + ((t - 1) & 1) * 8192 + row * 8 + (o >> 1) * 4;
            float l = b2r;
            #pragma unroll
            for (int w = 0; w < 8; w++) {
                float2 f2 = h22f2(*(const uint32_t*)(pb + w * 1024));
                l += (o & 1) ? f2.y : f2.x;
            }
            float m1 = fmaxf(l, __shfl_xor_sync(0xffffffffu, l, 1));
            float mx = fmaxf(m1, __shfl_xor_sync(0xffffffffu, m1, 2));
            float e = __expf(l - mx);
            float s = e + __shfl_xor_sync(0xffffffffu, e, 1);
            s += __shfl_xor_sync(0xffffffffu, s, 2);
            float lse = mx + __logf(s);
            int idx = sP[(t - 2) * TPC + row];
            float lpick = __shfl_sync(0xffffffffu, l, (lane & ~3) | idx);
            if ((lane & 3) == 0) acc += lpick - lse;
        }

        // ---------- gate epilogue (half2): h_t -> sA[(t+1)&1] ----------
        if (t < T_STEPS) {
            const uint32_t wbuf = (uint32_t)((t + 1) & 1) * A_BUFSZ;
            #pragma unroll
            for (int m = 0; m < 4; m++)
                #pragma unroll
                for (int rr = 0; rr < 2; rr++) {
                    int row = rbase + m * 16 + rg + rr * 8;
                    int v = (t > 0) ? sP[(t - 1) * TPC + row] : 0;
                    if (cg == 0 && c4 == 0) {
                        int vn = sP[t * TPC + row];
                        *(uint2*)(sm + S_A0 + wbuf + row * 272 + 256) =
                            make_uint2(f2h2((float)(vn & 1), (float)(vn >> 1)), f2h2(1.0f, 0.0f));
                    }
                    #pragma unroll
                    for (int f = 0; f < 2; f++) {
                        __half2 xn = baseN2[f];
                        if (v & 1) xn = __hadd2(xn, wN02[f]);
                        if (v & 2) xn = __hadd2(xn, wN12[f]);
                        __half2 r = __hfma2(tanh2h(__hmul2(u2h2(aR[m][f][rr]), h05)), h05, h05);
                        __half2 z = __hfma2(tanh2h(__hmul2(u2h2(aZ[m][f][rr]), h05)), h05, h05);
                        __half2 n = tanh2h(__hfma2(r, u2h2(aN[m][f][rr]), xn));
                        __half2 hprev = u2h2(hpH[m][f][rr]);
                        __half2 h = __hfma2(z, __hsub2(hprev, n), n);
                        uint32_t hu = h22u(h);
                        hpH[m][f][rr] = hu;
                        int col0 = j0 + f * 8 + 2 * c4;
                        *(uint32_t*)(sm + S_A0 + wbuf + row * 272 + col0 * 2) = hu;
                    }
                }
        }

        // ---------- head partials for step t-1 -> sPart[t&1] (f16x2) ----------
        if (t >= 1 && t <= T_STEPS) {
            float4 wci[4];
            #pragma unroll
            for (int ci = 0; ci < 4; ci++)
                wci[ci] = sW2T[j0 + (ci >> 1) * 8 + 2 * c4 + (ci & 1)];
            float p[8][4];
            #pragma unroll
            for (int q = 0; q < 8; q++)
                #pragma unroll
                for (int o = 0; o < 4; o++) p[q][o] = 0.0f;
            #pragma unroll
            for (int m = 0; m < 4; m++)
                #pragma unroll
                for (int f = 0; f < 2; f++)
                    #pragma unroll
                    for (int rr = 0; rr < 2; rr++) {
                        float2 hvv = h22f2(aH[m][f][rr]);
                        int q = m * 2 + rr;
                        #pragma unroll
                        for (int lo = 0; lo < 2; lo++) {
                            int ci = f * 2 + lo;
                            float hid = fmaxf(lo ? hvv.y : hvv.x, 0.0f);
                            p[q][0] = fmaf(hid, wci[ci].x, p[q][0]);
                            p[q][1] = fmaf(hid, wci[ci].y, p[q][1]);
                            p[q][2] = fmaf(hid, wci[ci].z, p[q][2]);
                            p[q][3] = fmaf(hid, wci[ci].w, p[q][3]);
                        }
                    }
            #pragma unroll
            for (int q = 0; q < 8; q++)
                #pragma unroll
                for (int o = 0; o < 4; o++) {
                    float v = p[q][o];
                    v += __shfl_xor_sync(0xffffffffu, v, 1);
                    v += __shfl_xor_sync(0xffffffffu, v, 2);
                    p[q][o] = v;
                }
            if (c4 == 0) {
                char* dst = sm + S_PART + (t & 1) * 8192 + cg * 1024;
                #pragma unroll
                for (int q = 0; q < 8; q++) {
                    int row = rbase + (q >> 1) * 16 + rg + (q & 1) * 8;
                    *(uint2*)(dst + row * 8) =
                        make_uint2(f2h2(p[q][0], p[q][1]), f2h2(p[q][2], p[q][3]));
                }
            }
        }
    }

    if ((lane & 3) == 0)
        out[bBase + rbase + cg * 8 + (lane >> 2)] = acc;
}

extern "C" void kernel_launch(void* const* d_in, const int* in_sizes, int n_in,
                              void* d_out, int out_size) {
    const float* x    = (const float*)d_in[0];
    const float* w_ih = (const float*)d_in[1];
    const float* w_hh = (const float*)d_in[2];
    const float* b_ih = (const float*)d_in[3];
    const float* b_hh = (const float*)d_in[4];
    const float* w1   = (const float*)d_in[5];
    const float* b1   = (const float*)d_in[6];
    const float* w2   = (const float*)d_in[7];
    const float* b2   = (const float*)d_in[8];
    float* out = (float*)d_out;

    cudaFuncSetAttribute(prnn_kernel, cudaFuncAttributeMaxDynamicSharedMemorySize, SMEM_TOTAL);
    prnn_kernel<<<NCTA, THREADS, SMEM_TOTAL>>>(
        x, w_ih, w_hh, b_ih, b_hh, w1, b1, w2, b2, out);
}